// round 14
// baseline (speedup 1.0000x reference)
#include <cuda_runtime.h>
#include <cuda_bf16.h>
#include <cstdint>

#define NHEADS 16
#define DH 64
#define BDIM 4
#define NDIM 2048
#define CDIM 1024
#define MROWS (BDIM * NDIM)  // 8192

// ---------------- scratch (static; no runtime allocs) -----------------------
// Unified tile layout: [blk(128 rows)][kchunk(32 k)][row: 128B = hi 4x16B | lo 4x16B]
// 16B chunk swizzle: chunk' = chunk ^ (rowin & 7)  (ldmatrix-compatible).
__device__ char g_x[(MROWS / 128) * (CDIM / 32) * 16384];
__device__ char g_wq[(3 * CDIM / 128) * (CDIM / 32) * 16384];
__device__ char g_wp[(CDIM / 128) * (CDIM / 32) * 16384];
__device__ char g_att[(MROWS / 128) * (CDIM / 32) * 16384];
__device__ char g_fq[BDIM * NHEADS * 16 * 32768];
__device__ char g_fk[BDIM * NHEADS * 16 * 32768];
__device__ char g_fv[BDIM * NHEADS * 16 * 32768];

#define QSCALE 0.18033688011112042f   // Dh^-0.5 * log2(e)
#define MASKVAL -14426950.4f          // -1e7 * log2(e)

__device__ __forceinline__ size_t utile_off(int row, int k, int K, int hilo) {
    const int blk = row >> 7, rowin = row & 127;
    const int kc = k >> 5;
    const int chunk = ((k & 31) >> 3) + hilo * 4;
    return (size_t)(blk * (K >> 5) + kc) * 16384 + rowin * 128 +
           ((chunk ^ (rowin & 7)) << 4) + (k & 7) * 2;
}

// ---------------- PTX helpers ------------------------------------------------
__device__ __forceinline__ uint32_t smem_u32(const void* p) {
    uint32_t a;
    asm("{ .reg .u64 t; cvta.to.shared.u64 t, %1; cvt.u32.u64 %0, t; }"
        : "=r"(a) : "l"(p));
    return a;
}
__device__ __forceinline__ uint32_t lds32(uint32_t a) {
    uint32_t v;
    asm volatile("ld.shared.b32 %0, [%1];" : "=r"(v) : "r"(a));
    return v;
}
__device__ __forceinline__ float ex2f(float x) {
    float r;
    asm("ex2.approx.f32 %0, %1;" : "=f"(r) : "f"(x));
    return r;
}
__device__ __forceinline__ void mbar_init(uint32_t a, uint32_t cnt) {
    asm volatile("mbarrier.init.shared.b64 [%0], %1;" :: "r"(a), "r"(cnt) : "memory");
}
__device__ __forceinline__ void mbar_expect(uint32_t a, uint32_t bytes) {
    asm volatile("mbarrier.arrive.expect_tx.shared.b64 _, [%0], %1;"
                 :: "r"(a), "r"(bytes) : "memory");
}
__device__ __forceinline__ void mbar_arrive(uint32_t a) {
    asm volatile("mbarrier.arrive.shared.b64 _, [%0];" :: "r"(a) : "memory");
}
__device__ __forceinline__ void mbar_wait(uint32_t a, uint32_t parity) {
    asm volatile(
        "{\n\t.reg .pred P1;\n"
        "WAIT_LOOP_%=:\n\t"
        "mbarrier.try_wait.parity.acquire.cta.shared::cta.b64 P1, [%0], %1, 0x989680;\n\t"
        "@P1 bra.uni WAIT_DONE_%=;\n\t"
        "bra.uni WAIT_LOOP_%=;\n"
        "WAIT_DONE_%=:\n\t}"
        :: "r"(a), "r"(parity) : "memory");
}
__device__ __forceinline__ void bulk_g2s(uint32_t dst, const void* src,
                                         uint32_t bytes, uint32_t mbar) {
    asm volatile(
        "cp.async.bulk.shared::cluster.global.mbarrier::complete_tx::bytes "
        "[%0], [%1], %2, [%3];"
        :: "r"(dst), "l"(src), "r"(bytes), "r"(mbar) : "memory");
}
__device__ __forceinline__ void mma16816(float* c, const uint32_t* a,
                                         const uint32_t* b) {
    asm volatile(
        "mma.sync.aligned.m16n8k16.row.col.f32.bf16.bf16.f32 "
        "{%0,%1,%2,%3}, {%4,%5,%6,%7}, {%8,%9}, {%0,%1,%2,%3};"
        : "+f"(c[0]), "+f"(c[1]), "+f"(c[2]), "+f"(c[3])
        : "r"(a[0]), "r"(a[1]), "r"(a[2]), "r"(a[3]), "r"(b[0]), "r"(b[1]));
}
#define LDMX4(r0, r1, r2, r3, addr) \
    asm volatile("ldmatrix.sync.aligned.m8n8.x4.shared.b16 {%0,%1,%2,%3}, [%4];" \
                 : "=r"(r0), "=r"(r1), "=r"(r2), "=r"(r3) : "r"(addr))

__device__ __forceinline__ void split_bf16(float v, __nv_bfloat16& h, __nv_bfloat16& l) {
    h = __float2bfloat16(v);
    l = __float2bfloat16(v - __bfloat162float(h));
}
__device__ __forceinline__ uint32_t b2u(__nv_bfloat162 v) {
    return *reinterpret_cast<uint32_t*>(&v);
}
__device__ __forceinline__ void split_pack(float a, float b, uint32_t& hi, uint32_t& lo) {
    __nv_bfloat162 h = __floats2bfloat162_rn(a, b);
    __nv_bfloat162 l = __floats2bfloat162_rn(a - __bfloat162float(h.x),
                                             b - __bfloat162float(h.y));
    hi = b2u(h); lo = b2u(l);
}

// ---------------------------------------------------------------------------
// Prep: fp32 [M,K] row-major -> unified tiled bf16 (hi|lo rows)
// ---------------------------------------------------------------------------
__global__ void split_tile(const float4* __restrict__ in, char* __restrict__ dst,
                           int K, int n4) {
    int i = blockIdx.x * 256 + threadIdx.x;
    if (i >= n4) return;
    const int K4 = K >> 2;
    const int row = i / K4, k = (i % K4) << 2;
    float4 v = in[i];
    uint32_t h0, l0, h1, l1;
    split_pack(v.x, v.y, h0, l0);
    split_pack(v.z, v.w, h1, l1);
    *reinterpret_cast<uint2*>(dst + utile_off(row, k, K, 0)) = make_uint2(h0, h1);
    *reinterpret_cast<uint2*>(dst + utile_off(row, k, K, 1)) = make_uint2(l0, l1);
}

// W [K,Nn] -> W^T unified tiled ([Nn rows, K cols])
__global__ void tsplit_tile(const float* __restrict__ W, char* __restrict__ dst,
                            int K, int Nn) {
    __shared__ float t[32][33];
    const int n0 = blockIdx.x * 32, k0 = blockIdx.y * 32;
    const int tx = threadIdx.x, ty = threadIdx.y;  // (32, 8)
    #pragma unroll
    for (int i = 0; i < 4; i++) {
        const int k = k0 + ty + i * 8;
        t[ty + i * 8][tx] = W[(size_t)k * Nn + n0 + tx];
    }
    __syncthreads();
    const int tid = ty * 32 + tx;
    const int nl = tid >> 3, kl = (tid & 7) << 2;
    uint32_t h0, l0, h1, l1;
    split_pack(t[kl][nl],     t[kl + 1][nl], h0, l0);
    split_pack(t[kl + 2][nl], t[kl + 3][nl], h1, l1);
    *reinterpret_cast<uint2*>(dst + utile_off(n0 + nl, k0 + kl, K, 0)) = make_uint2(h0, h1);
    *reinterpret_cast<uint2*>(dst + utile_off(n0 + nl, k0 + kl, K, 1)) = make_uint2(l0, l1);
}

// ---------------------------------------------------------------------------
// Shared GEMM mainloop: 3-stage bulk pipeline, ldmatrix fragment loads.
// ---------------------------------------------------------------------------
__device__ __forceinline__ void gemm_mainloop(
    uint32_t sb, int tid, int wid, int lane,
    const char* Ahl, const char* Bhl,
    size_t tbA, size_t tbB, int Kc, float cfr[2][8][4])
{
    const int wm = wid & 3, wn = wid >> 2;

    const uint32_t lA = (uint32_t)((lane & 7) + ((lane >> 3) & 1) * 8);
    const uint32_t cA = (uint32_t)(lane >> 4);
    const uint32_t lB = (uint32_t)((lane & 7) + (lane >> 4) * 8);
    const uint32_t cB = (uint32_t)((lane >> 3) & 1);

    auto produce = [&](int p) {
        const int s = p % 3;
        const uint32_t st = sb + 1024 + s * 32768;
        mbar_expect(sb + s * 8, 32768);
        bulk_g2s(st,         Ahl + (tbA + p) * 16384, 16384, sb + s * 8);
        bulk_g2s(st + 16384, Bhl + (tbB + p) * 16384, 16384, sb + s * 8);
    };

    if (tid == 0) { produce(0); produce(1); }

    for (int c = 0; c < Kc; c++) {
        const int cs = c % 3, cph = (c / 3) & 1;
        if (tid == 0) {
            const int p = c + 2;
            if (p < Kc) {
                const int ps = p % 3;
                if (p >= 3) mbar_wait(sb + 32 + ps * 8, (uint32_t)(((p / 3) - 1) & 1));
                produce(p);
            }
        }
        mbar_wait(sb + cs * 8, (uint32_t)cph);

        const uint32_t st = sb + 1024 + cs * 32768;
        #pragma unroll
        for (int ks = 0; ks < 2; ks++) {
            uint32_t ah[2][4], al[2][4];
            #pragma unroll
            for (int mt = 0; mt < 2; mt++) {
                const uint32_t row = (uint32_t)(wm * 32 + mt * 16) + lA;
                const uint32_t rb = st + row * 128;
                LDMX4(ah[mt][0], ah[mt][1], ah[mt][2], ah[mt][3],
                      rb + (((2 * ks + cA) ^ (row & 7)) << 4));
                LDMX4(al[mt][0], al[mt][1], al[mt][2], al[mt][3],
                      rb + (((2 * ks + cA + 4) ^ (row & 7)) << 4));
            }
            #pragma unroll
            for (int p = 0; p < 4; p++) {
                const uint32_t row = (uint32_t)(wn * 64 + p * 16) + lB;
                const uint32_t rb = st + 16384 + row * 128;
                uint32_t h0, h1, h2, h3, l0, l1, l2, l3;
                LDMX4(h0, h1, h2, h3, rb + (((2 * ks + cB) ^ (row & 7)) << 4));
                LDMX4(l0, l1, l2, l3, rb + (((2 * ks + cB + 4) ^ (row & 7)) << 4));
                uint32_t bh0[2] = {h0, h1}, bh1[2] = {h2, h3};
                uint32_t bl0[2] = {l0, l1}, bl1[2] = {l2, l3};
                #pragma unroll
                for (int mt = 0; mt < 2; mt++) {
                    mma16816(cfr[mt][2 * p],     ah[mt], bh0);
                    mma16816(cfr[mt][2 * p],     ah[mt], bl0);
                    mma16816(cfr[mt][2 * p],     al[mt], bh0);
                    mma16816(cfr[mt][2 * p + 1], ah[mt], bh1);
                    mma16816(cfr[mt][2 * p + 1], ah[mt], bl1);
                    mma16816(cfr[mt][2 * p + 1], al[mt], bh1);
                }
            }
        }
        mbar_arrive(sb + 32 + cs * 8);
    }
}

__device__ __forceinline__ void gemm_barrier_init(uint32_t sb, int tid) {
    if (tid == 0) {
        #pragma unroll
        for (int s = 0; s < 3; s++) {
            mbar_init(sb + s * 8, 1);
            mbar_init(sb + 32 + s * 8, 256);
        }
        asm volatile("fence.proxy.async.shared::cta;" ::: "memory");
    }
    __syncthreads();
}

// ---------------------------------------------------------------------------
// Generic HMMA GEMM (proj): fp32 epilogue + bias
// ---------------------------------------------------------------------------
__global__ __launch_bounds__(256, 2) void gemm_hmma(
    const char* __restrict__ Ahl, const char* __restrict__ Bhl,
    const float* __restrict__ bias, float* __restrict__ Cout,
    int M, int Nn, int K)
{
    extern __shared__ char smem[];
    const uint32_t sb = smem_u32(smem);
    const int tid = threadIdx.x, wid = tid >> 5, lane = tid & 31;
    const int gid = lane >> 2, tig = lane & 3;
    const int wm = wid & 3, wn = wid >> 2;
    const int Kc = K >> 5;

    gemm_barrier_init(sb, tid);

    float cfr[2][8][4];
    #pragma unroll
    for (int mt = 0; mt < 2; mt++)
        #pragma unroll
        for (int nt = 0; nt < 8; nt++)
            #pragma unroll
            for (int q = 0; q < 4; q++) cfr[mt][nt][q] = 0.f;

    gemm_mainloop(sb, tid, wid, lane, Ahl, Bhl,
                  (size_t)blockIdx.y * Kc, (size_t)blockIdx.x * Kc, Kc, cfr);

    const int m0 = blockIdx.y * 128, n0 = blockIdx.x * 128;
    #pragma unroll
    for (int mt = 0; mt < 2; mt++) {
        const int r = m0 + wm * 32 + mt * 16 + gid;
        #pragma unroll
        for (int nt = 0; nt < 8; nt++) {
            const int col = n0 + wn * 64 + nt * 8 + tig * 2;
            float b0 = bias ? bias[col] : 0.f;
            float b1 = bias ? bias[col + 1] : 0.f;
            *reinterpret_cast<float2*>(&Cout[(size_t)r * Nn + col]) =
                make_float2(cfr[mt][nt][0] + b0, cfr[mt][nt][1] + b1);
            *reinterpret_cast<float2*>(&Cout[(size_t)(r + 8) * Nn + col]) =
                make_float2(cfr[mt][nt][2] + b0, cfr[mt][nt][3] + b1);
        }
    }
}

// ---------------------------------------------------------------------------
// QKV GEMM with fused flash-tile epilogue (Q scaled by QSCALE).
// ---------------------------------------------------------------------------
__global__ __launch_bounds__(256, 2) void gemm_qkv(
    const char* __restrict__ Ahl, const char* __restrict__ Bhl,
    char* __restrict__ fq, char* __restrict__ fk, char* __restrict__ fv)
{
    extern __shared__ char smem[];
    const uint32_t sb = smem_u32(smem);
    const int tid = threadIdx.x, wid = tid >> 5, lane = tid & 31;
    const int gid = lane >> 2, tig = lane & 3;
    const int wm = wid & 3, wn = wid >> 2;
    constexpr int Kc = CDIM >> 5;  // 32

    gemm_barrier_init(sb, tid);

    float cfr[2][8][4];
    #pragma unroll
    for (int mt = 0; mt < 2; mt++)
        #pragma unroll
        for (int nt = 0; nt < 8; nt++)
            #pragma unroll
            for (int q = 0; q < 4; q++) cfr[mt][nt][q] = 0.f;

    gemm_mainloop(sb, tid, wid, lane, Ahl, Bhl,
                  (size_t)blockIdx.y * Kc, (size_t)blockIdx.x * Kc, Kc, cfr);

    const int b = blockIdx.y >> 4, tile = blockIdx.y & 15;
    const int bx = blockIdx.x;

    if (bx < 16) {
        const bool isQ = bx < 8;
        const int j = isQ ? bx : bx - 8;
        char* const fbase = isQ ? fq : fk;
        const float sc = isQ ? QSCALE : 1.0f;
        #pragma unroll
        for (int mt = 0; mt < 2; mt++) {
            const int rA = wm * 32 + mt * 16 + gid;
            #pragma unroll
            for (int nt = 0; nt < 8; nt++) {
                const int c = wn * 64 + nt * 8 + tig * 2;
                const int h = 2 * j + (c >> 6);
                const int d = c & 63;
                char* dst = fbase + (((size_t)b * NHEADS + h) * 16 + tile) * 32768;
                const int kc = d >> 5, chunk = (d & 31) >> 3, bo = (d & 7) * 2;
                uint32_t hi0, lo0, hi1, lo1;
                split_pack(cfr[mt][nt][0] * sc, cfr[mt][nt][1] * sc, hi0, lo0);
                split_pack(cfr[mt][nt][2] * sc, cfr[mt][nt][3] * sc, hi1, lo1);
                char* baseA = dst + kc * 16384 + rA * 128;
                char* baseB = dst + kc * 16384 + (rA + 8) * 128;
                *reinterpret_cast<uint32_t*>(baseA + (((chunk)     ^ (rA & 7)) << 4) + bo) = hi0;
                *reinterpret_cast<uint32_t*>(baseA + (((chunk + 4) ^ (rA & 7)) << 4) + bo) = lo0;
                *reinterpret_cast<uint32_t*>(baseB + (((chunk)     ^ ((rA + 8) & 7)) << 4) + bo) = hi1;
                *reinterpret_cast<uint32_t*>(baseB + (((chunk + 4) ^ ((rA + 8) & 7)) << 4) + bo) = lo1;
            }
        }
    } else {
        const int j = bx - 16;
        float* vs = reinterpret_cast<float*>(smem + 1024);
        constexpr int VST = 130;
        __syncthreads();
        #pragma unroll
        for (int mt = 0; mt < 2; mt++) {
            const int rA = wm * 32 + mt * 16 + gid;
            #pragma unroll
            for (int nt = 0; nt < 8; nt++) {
                const int c = wn * 64 + nt * 8 + tig * 2;
                vs[rA * VST + c]           = cfr[mt][nt][0];
                vs[rA * VST + c + 1]       = cfr[mt][nt][1];
                vs[(rA + 8) * VST + c]     = cfr[mt][nt][2];
                vs[(rA + 8) * VST + c + 1] = cfr[mt][nt][3];
            }
        }
        __syncthreads();
        for (int it = tid; it < 4096; it += 256) {
            const int hsel = it >> 11, rem = it & 2047;
            const int d = rem >> 5, k4 = (rem & 31) * 4;
            const int cc = hsel * 64 + d;
            float4 v = make_float4(vs[k4 * VST + cc], vs[(k4 + 1) * VST + cc],
                                   vs[(k4 + 2) * VST + cc], vs[(k4 + 3) * VST + cc]);
            uint32_t h0, l0, h1, l1;
            split_pack(v.x, v.y, h0, l0);
            split_pack(v.z, v.w, h1, l1);
            char* vdst = fv + (((size_t)b * NHEADS + 2 * j + hsel) * 16 + tile) * 32768;
            const int kc = k4 >> 5, chunk = (k4 & 31) >> 3, bo = (k4 & 7) * 2;
            char* base = vdst + kc * 8192 + d * 128;
            *reinterpret_cast<uint2*>(base + (((chunk)     ^ (d & 7)) << 4) + bo) =
                make_uint2(h0, h1);
            *reinterpret_cast<uint2*>(base + (((chunk + 4) ^ (d & 7)) << 4) + bo) =
                make_uint2(l0, l1);
        }
    }
}

// ---------------------------------------------------------------------------
// HMMA flash attention: 128-key tiles, 2-stage pipeline, 1 CTA/SM.
// DUAL-TILE LOOKAHEAD: per iteration, S of BOTH resident tiles is issued
// before either softmax, so each softmax phase overlaps queued HMMA drain.
// Online-softmax update order (a then b) and all fp orders match R13 exactly.
// ---------------------------------------------------------------------------
__global__ __launch_bounds__(256, 1) void flash_hmma(
    const char* __restrict__ fq, const char* __restrict__ fk,
    const char* __restrict__ fv, const int* __restrict__ mask,
    char* __restrict__ outt)
{
    extern __shared__ char smem[];
    const uint32_t sb = smem_u32(smem);
    const int tid = threadIdx.x, w = tid >> 5, lane = tid & 31;
    const int gid = lane >> 2, tig = lane & 3;
    const int qt = blockIdx.x, h = blockIdx.y, b = blockIdx.z;
    const size_t bh = (size_t)b * NHEADS + h;

    const uint32_t QS = sb + 1024;
    const uint32_t ST0 = QS + 32768;
    constexpr uint32_t STG = 66560;

    if (tid == 0) {
        mbar_init(sb + 0, 1);
        mbar_init(sb + 8, 1);  mbar_init(sb + 16, 1);
        mbar_init(sb + 24, 256); mbar_init(sb + 32, 256);
        asm volatile("fence.proxy.async.shared::cta;" ::: "memory");
    }
    __syncthreads();

    auto produce = [&](int kt) {
        const int s = kt & 1;
        const uint32_t st = ST0 + s * STG;
        mbar_expect(sb + 8 + s * 8, 65536 + 512);
        bulk_g2s(st,         fk + (bh * 16 + kt) * 32768, 32768, sb + 8 + s * 8);
        bulk_g2s(st + 32768, fv + (bh * 16 + kt) * 32768, 32768, sb + 8 + s * 8);
        bulk_g2s(st + 65536, (const char*)(mask + b * NDIM + kt * 128), 512, sb + 8 + s * 8);
    };

    if (tid == 0) {
        mbar_expect(sb + 0, 32768);
        bulk_g2s(QS, fq + (bh * 16 + qt) * 32768, 32768, sb + 0);
        produce(0); produce(1);
    }

    mbar_wait(sb + 0, 0);
    uint32_t qh[4][4], ql[4][4];
    {
        const uint32_t r0 = (uint32_t)(w * 16 + gid);
        #pragma unroll
        for (int ks = 0; ks < 4; ks++) {
            const uint32_t kc = ks >> 1, cb = 2 * (ks & 1);
            const uint32_t a0 = QS + kc * 16384 + tig * 4;
            const uint32_t rA = r0, rB = r0 + 8;
            qh[ks][0] = lds32(a0 + rA * 128 + (((cb)     ^ (rA & 7)) << 4));
            qh[ks][1] = lds32(a0 + rB * 128 + (((cb)     ^ (rB & 7)) << 4));
            qh[ks][2] = lds32(a0 + rA * 128 + (((cb + 1) ^ (rA & 7)) << 4));
            qh[ks][3] = lds32(a0 + rB * 128 + (((cb + 1) ^ (rB & 7)) << 4));
            ql[ks][0] = lds32(a0 + rA * 128 + (((cb + 4) ^ (rA & 7)) << 4));
            ql[ks][1] = lds32(a0 + rB * 128 + (((cb + 4) ^ (rB & 7)) << 4));
            ql[ks][2] = lds32(a0 + rA * 128 + (((cb + 5) ^ (rA & 7)) << 4));
            ql[ks][3] = lds32(a0 + rB * 128 + (((cb + 5) ^ (rB & 7)) << 4));
        }
    }

    float o[8][4];
    #pragma unroll
    for (int nt = 0; nt < 8; nt++)
        #pragma unroll
        for (int q = 0; q < 4; q++) o[nt][q] = 0.f;
    float mi0 = -1e30f, mi1 = -1e30f, li0 = 0.f, li1 = 0.f;

    const uint32_t lrow = (uint32_t)(lane & 7);
    const uint32_t lch = (uint32_t)(lane >> 3);

    // S = Q @ K^T (3-pass) into sf from K tile at kbse
    auto s_comp = [&](float (&sf)[16][4], uint32_t kbse) {
        #pragma unroll
        for (int j = 0; j < 16; j++) {
            sf[j][0] = sf[j][1] = sf[j][2] = sf[j][3] = 0.f;
            const uint32_t row = (uint32_t)(j * 8) + lrow;
            #pragma unroll
            for (int kc = 0; kc < 2; kc++) {
                const uint32_t rb = kbse + kc * 16384 + row * 128;
                uint32_t h0, h1, h2, h3, l0, l1, l2, l3;
                LDMX4(h0, h1, h2, h3, rb + (((lch)     ^ (row & 7)) << 4));
                LDMX4(l0, l1, l2, l3, rb + (((lch + 4) ^ (row & 7)) << 4));
                uint32_t bh0[2] = {h0, h1}, bh1[2] = {h2, h3};
                uint32_t bl0[2] = {l0, l1}, bl1[2] = {l2, l3};
                mma16816(sf[j], qh[2 * kc],     bh0);
                mma16816(sf[j], qh[2 * kc],     bl0);
                mma16816(sf[j], ql[2 * kc],     bh0);
                mma16816(sf[j], qh[2 * kc + 1], bh1);
                mma16816(sf[j], qh[2 * kc + 1], bl1);
                mma16816(sf[j], ql[2 * kc + 1], bh1);
            }
        }
    };

    // mask + online softmax + interleaved exp/PV for one tile
    auto tile_tail = [&](float (&sf)[16][4], uint32_t vbse, uint32_t mbse) {
        #pragma unroll
        for (int j = 0; j < 16; j++) {
            const uint32_t ma = mbse + (uint32_t)(j * 8 + 2 * tig) * 4;
            if ((int)lds32(ma) > 0)     { sf[j][0] = MASKVAL; sf[j][2] = MASKVAL; }
            if ((int)lds32(ma + 4) > 0) { sf[j][1] = MASKVAL; sf[j][3] = MASKVAL; }
        }

        float rm0 = -1e30f, rm1 = -1e30f;
        #pragma unroll
        for (int j = 0; j < 16; j++) {
            rm0 = fmaxf(rm0, fmaxf(sf[j][0], sf[j][1]));
            rm1 = fmaxf(rm1, fmaxf(sf[j][2], sf[j][3]));
        }
        rm0 = fmaxf(rm0, __shfl_xor_sync(0xffffffffu, rm0, 1));
        rm0 = fmaxf(rm0, __shfl_xor_sync(0xffffffffu, rm0, 2));
        rm1 = fmaxf(rm1, __shfl_xor_sync(0xffffffffu, rm1, 1));
        rm1 = fmaxf(rm1, __shfl_xor_sync(0xffffffffu, rm1, 2));
        const float mn0 = fmaxf(mi0, rm0), mn1 = fmaxf(mi1, rm1);
        const float a0 = ex2f(mi0 - mn0), a1 = ex2f(mi1 - mn1);
        mi0 = mn0; mi1 = mn1;
        #pragma unroll
        for (int nt = 0; nt < 8; nt++) {
            o[nt][0] *= a0; o[nt][1] *= a0;
            o[nt][2] *= a1; o[nt][3] *= a1;
        }

        float rs0 = 0.f, rs1 = 0.f;
        #pragma unroll
        for (int kc = 0; kc < 4; kc++) {
            uint32_t pah[2][4], pal[2][4];
            #pragma unroll
            for (int jj = 0; jj < 2; jj++) {
                const int j0 = 4 * kc + 2 * jj;
                sf[j0][0] = ex2f(sf[j0][0] - mn0); rs0 += sf[j0][0];
                sf[j0][1] = ex2f(sf[j0][1] - mn0); rs0 += sf[j0][1];
                sf[j0][2] = ex2f(sf[j0][2] - mn1); rs1 += sf[j0][2];
                sf[j0][3] = ex2f(sf[j0][3] - mn1); rs1 += sf[j0][3];
                sf[j0 + 1][0] = ex2f(sf[j0 + 1][0] - mn0); rs0 += sf[j0 + 1][0];
                sf[j0 + 1][1] = ex2f(sf[j0 + 1][1] - mn0); rs0 += sf[j0 + 1][1];
                sf[j0 + 1][2] = ex2f(sf[j0 + 1][2] - mn1); rs1 += sf[j0 + 1][2];
                sf[j0 + 1][3] = ex2f(sf[j0 + 1][3] - mn1); rs1 += sf[j0 + 1][3];
                split_pack(sf[j0][0],     sf[j0][1],     pah[jj][0], pal[jj][0]);
                split_pack(sf[j0][2],     sf[j0][3],     pah[jj][1], pal[jj][1]);
                split_pack(sf[j0 + 1][0], sf[j0 + 1][1], pah[jj][2], pal[jj][2]);
                split_pack(sf[j0 + 1][2], sf[j0 + 1][3], pah[jj][3], pal[jj][3]);
            }
            #pragma unroll
            for (int nt = 0; nt < 8; nt++) {
                const uint32_t row = (uint32_t)(nt * 8) + lrow;
                const uint32_t rb = vbse + kc * 8192 + row * 128;
                uint32_t h0, h1, h2, h3, l0, l1, l2, l3;
                LDMX4(h0, h1, h2, h3, rb + (((lch)     ^ (row & 7)) << 4));
                LDMX4(l0, l1, l2, l3, rb + (((lch + 4) ^ (row & 7)) << 4));
                uint32_t vh0[2] = {h0, h1}, vh1[2] = {h2, h3};
                uint32_t vl0[2] = {l0, l1}, vl1[2] = {l2, l3};
                mma16816(o[nt], pah[0], vh0);
                mma16816(o[nt], pah[0], vl0);
                mma16816(o[nt], pal[0], vh0);
                mma16816(o[nt], pah[1], vh1);
                mma16816(o[nt], pah[1], vl1);
                mma16816(o[nt], pal[1], vh1);
            }
        }

        rs0 += __shfl_xor_sync(0xffffffffu, rs0, 1);
        rs0 += __shfl_xor_sync(0xffffffffu, rs0, 2);
        rs1 += __shfl_xor_sync(0xffffffffu, rs1, 1);
        rs1 += __shfl_xor_sync(0xffffffffu, rs1, 2);
        li0 = li0 * a0 + rs0;
        li1 = li1 * a1 + rs1;
    };

    #pragma unroll 1
    for (int it = 0; it < 8; it++) {
        const uint32_t par = (uint32_t)(it & 1);
        // ---- S of tile a (stage 0), then S of tile b (stage 1) ----
        mbar_wait(sb + 8, par);
        float sfa[16][4];
        s_comp(sfa, ST0);
        mbar_wait(sb + 16, par);
        float sfb[16][4];
        s_comp(sfb, ST0 + STG);

        // ---- tile a tail (softmax overlaps queued S(b) HMMAs) ----
        tile_tail(sfa, ST0 + 32768, ST0 + 65536);
        mbar_arrive(sb + 24);
        if (tid == 0 && 2 * it + 2 < 16) {
            mbar_wait(sb + 24, par);
            produce(2 * it + 2);
        }

        // ---- tile b tail (softmax overlaps queued PV(a) HMMAs) ----
        tile_tail(sfb, ST0 + STG + 32768, ST0 + STG + 65536);
        mbar_arrive(sb + 32);
        if (tid == 0 && 2 * it + 3 < 16) {
            mbar_wait(sb + 32, par);
            produce(2 * it + 3);
        }
    }

    // ---- epilogue: normalize, emit unified tiled bf16 (hi|lo) ----
    const float inv0 = 1.f / li0, inv1 = 1.f / li1;
    const int row0 = b * NDIM + qt * 128 + w * 16 + gid;
    #pragma unroll
    for (int nt = 0; nt < 8; nt++) {
        const int col = h * 64 + nt * 8 + tig * 2;
        uint32_t h0, l0, h1, l1;
        split_pack(o[nt][0] * inv0, o[nt][1] * inv0, h0, l0);
        split_pack(o[nt][2] * inv1, o[nt][3] * inv1, h1, l1);
        *reinterpret_cast<uint32_t*>(outt + utile_off(row0, col, CDIM, 0)) = h0;
        *reinterpret_cast<uint32_t*>(outt + utile_off(row0, col, CDIM, 1)) = l0;
        *reinterpret_cast<uint32_t*>(outt + utile_off(row0 + 8, col, CDIM, 0)) = h1;
        *reinterpret_cast<uint32_t*>(outt + utile_off(row0 + 8, col, CDIM, 1)) = l1;
    }
}

// ---------------------------------------------------------------------------
extern "C" void kernel_launch(void* const* d_in, const int* in_sizes, int n_in,
                              void* d_out, int out_size)
{
    const float* x     = (const float*)d_in[0];
    const float* Wqkv  = (const float*)d_in[1];
    const float* Wproj = (const float*)d_in[2];
    const float* bproj = (const float*)d_in[3];
    const int*   mask  = (const int*)d_in[4];
    float* out = (float*)d_out;

    const int B = BDIM, N = NDIM, C = CDIM, M = MROWS;

    char *x_p, *wq_p, *wp_p, *att_p, *fq_p, *fk_p, *fv_p;
    cudaGetSymbolAddress((void**)&x_p, g_x);
    cudaGetSymbolAddress((void**)&wq_p, g_wq);
    cudaGetSymbolAddress((void**)&wp_p, g_wp);
    cudaGetSymbolAddress((void**)&att_p, g_att);
    cudaGetSymbolAddress((void**)&fq_p, g_fq);
    cudaGetSymbolAddress((void**)&fk_p, g_fk);
    cudaGetSymbolAddress((void**)&fv_p, g_fv);

    // Prep
    const int n4 = M * C / 4;
    split_tile<<<(n4 + 255) / 256, 256>>>((const float4*)x, x_p, C, n4);
    tsplit_tile<<<dim3(3 * C / 32, C / 32), dim3(32, 8)>>>(Wqkv, wq_p, C, 3 * C);
    tsplit_tile<<<dim3(C / 32, C / 32), dim3(32, 8)>>>(Wproj, wp_p, C, C);

    const int gsmem = 1024 + 3 * 32768;
    cudaFuncSetAttribute(gemm_qkv, cudaFuncAttributeMaxDynamicSharedMemorySize, gsmem);
    cudaFuncSetAttribute(gemm_hmma, cudaFuncAttributeMaxDynamicSharedMemorySize, gsmem);

    // 1) QKV GEMM with fused flash-tile epilogue
    gemm_qkv<<<dim3(3 * C / 128, M / 128), 256, gsmem>>>(
        x_p, wq_p, fq_p, fk_p, fv_p);

    // 2) Flash attention (HMMA, ex2 softmax, dual-tile lookahead)
    const int fsmem = 1024 + 32768 + 2 * 66560;
    cudaFuncSetAttribute(flash_hmma, cudaFuncAttributeMaxDynamicSharedMemorySize, fsmem);
    flash_hmma<<<dim3(16, NHEADS, B), 256, fsmem>>>(
        fq_p, fk_p, fv_p, mask, att_p);

    // 3) Output projection
    gemm_hmma<<<dim3(C / 128, M / 128), 256, gsmem>>>(
        att_p, wp_p, bproj, out, M, C, C);
}

// round 15
// speedup vs baseline: 1.5829x; 1.5829x over previous
#include <cuda_runtime.h>
#include <cuda_bf16.h>
#include <cstdint>

#define NHEADS 16
#define DH 64
#define BDIM 4
#define NDIM 2048
#define CDIM 1024
#define MROWS (BDIM * NDIM)  // 8192

// ---------------- scratch (static; no runtime allocs) -----------------------
// Unified tile layout: [blk(128 rows)][kchunk(32 k)][row: 128B = hi 4x16B | lo 4x16B]
// 16B chunk swizzle: chunk' = chunk ^ (rowin & 7)  (ldmatrix-compatible).
__device__ char g_x[(MROWS / 128) * (CDIM / 32) * 16384];
__device__ char g_wq[(3 * CDIM / 128) * (CDIM / 32) * 16384];
__device__ char g_wp[(CDIM / 128) * (CDIM / 32) * 16384];
__device__ char g_att[(MROWS / 128) * (CDIM / 32) * 16384];
__device__ char g_fq[BDIM * NHEADS * 16 * 32768];
__device__ char g_fk[BDIM * NHEADS * 16 * 32768];
__device__ char g_fv[BDIM * NHEADS * 16 * 32768];

#define QSCALE 0.18033688011112042f   // Dh^-0.5 * log2(e)
#define MASKVAL -14426950.4f          // -1e7 * log2(e)

__device__ __forceinline__ size_t utile_off(int row, int k, int K, int hilo) {
    const int blk = row >> 7, rowin = row & 127;
    const int kc = k >> 5;
    const int chunk = ((k & 31) >> 3) + hilo * 4;
    return (size_t)(blk * (K >> 5) + kc) * 16384 + rowin * 128 +
           ((chunk ^ (rowin & 7)) << 4) + (k & 7) * 2;
}

// ---------------- PTX helpers ------------------------------------------------
__device__ __forceinline__ uint32_t smem_u32(const void* p) {
    uint32_t a;
    asm("{ .reg .u64 t; cvta.to.shared.u64 t, %1; cvt.u32.u64 %0, t; }"
        : "=r"(a) : "l"(p));
    return a;
}
__device__ __forceinline__ uint32_t lds32(uint32_t a) {
    uint32_t v;
    asm volatile("ld.shared.b32 %0, [%1];" : "=r"(v) : "r"(a));
    return v;
}
__device__ __forceinline__ float ex2f(float x) {
    float r;
    asm("ex2.approx.f32 %0, %1;" : "=f"(r) : "f"(x));
    return r;
}
__device__ __forceinline__ void mbar_init(uint32_t a, uint32_t cnt) {
    asm volatile("mbarrier.init.shared.b64 [%0], %1;" :: "r"(a), "r"(cnt) : "memory");
}
__device__ __forceinline__ void mbar_expect(uint32_t a, uint32_t bytes) {
    asm volatile("mbarrier.arrive.expect_tx.shared.b64 _, [%0], %1;"
                 :: "r"(a), "r"(bytes) : "memory");
}
__device__ __forceinline__ void mbar_arrive(uint32_t a) {
    asm volatile("mbarrier.arrive.shared.b64 _, [%0];" :: "r"(a) : "memory");
}
__device__ __forceinline__ void mbar_wait(uint32_t a, uint32_t parity) {
    asm volatile(
        "{\n\t.reg .pred P1;\n"
        "WAIT_LOOP_%=:\n\t"
        "mbarrier.try_wait.parity.acquire.cta.shared::cta.b64 P1, [%0], %1, 0x989680;\n\t"
        "@P1 bra.uni WAIT_DONE_%=;\n\t"
        "bra.uni WAIT_LOOP_%=;\n"
        "WAIT_DONE_%=:\n\t}"
        :: "r"(a), "r"(parity) : "memory");
}
__device__ __forceinline__ void bulk_g2s(uint32_t dst, const void* src,
                                         uint32_t bytes, uint32_t mbar) {
    asm volatile(
        "cp.async.bulk.shared::cluster.global.mbarrier::complete_tx::bytes "
        "[%0], [%1], %2, [%3];"
        :: "r"(dst), "l"(src), "r"(bytes), "r"(mbar) : "memory");
}
__device__ __forceinline__ void mma16816(float* c, const uint32_t* a,
                                         const uint32_t* b) {
    asm volatile(
        "mma.sync.aligned.m16n8k16.row.col.f32.bf16.bf16.f32 "
        "{%0,%1,%2,%3}, {%4,%5,%6,%7}, {%8,%9}, {%0,%1,%2,%3};"
        : "+f"(c[0]), "+f"(c[1]), "+f"(c[2]), "+f"(c[3])
        : "r"(a[0]), "r"(a[1]), "r"(a[2]), "r"(a[3]), "r"(b[0]), "r"(b[1]));
}
#define LDMX4(r0, r1, r2, r3, addr) \
    asm volatile("ldmatrix.sync.aligned.m8n8.x4.shared.b16 {%0,%1,%2,%3}, [%4];" \
                 : "=r"(r0), "=r"(r1), "=r"(r2), "=r"(r3) : "r"(addr))

__device__ __forceinline__ void split_bf16(float v, __nv_bfloat16& h, __nv_bfloat16& l) {
    h = __float2bfloat16(v);
    l = __float2bfloat16(v - __bfloat162float(h));
}
__device__ __forceinline__ uint32_t b2u(__nv_bfloat162 v) {
    return *reinterpret_cast<uint32_t*>(&v);
}
__device__ __forceinline__ void split_pack(float a, float b, uint32_t& hi, uint32_t& lo) {
    __nv_bfloat162 h = __floats2bfloat162_rn(a, b);
    __nv_bfloat162 l = __floats2bfloat162_rn(a - __bfloat162float(h.x),
                                             b - __bfloat162float(h.y));
    hi = b2u(h); lo = b2u(l);
}

// ---------------------------------------------------------------------------
// Prep: fp32 [M,K] row-major -> unified tiled bf16 (hi|lo rows)
// ---------------------------------------------------------------------------
__global__ void split_tile(const float4* __restrict__ in, char* __restrict__ dst,
                           int K, int n4) {
    int i = blockIdx.x * 256 + threadIdx.x;
    if (i >= n4) return;
    const int K4 = K >> 2;
    const int row = i / K4, k = (i % K4) << 2;
    float4 v = in[i];
    uint32_t h0, l0, h1, l1;
    split_pack(v.x, v.y, h0, l0);
    split_pack(v.z, v.w, h1, l1);
    *reinterpret_cast<uint2*>(dst + utile_off(row, k, K, 0)) = make_uint2(h0, h1);
    *reinterpret_cast<uint2*>(dst + utile_off(row, k, K, 1)) = make_uint2(l0, l1);
}

// W [K,Nn] -> W^T unified tiled ([Nn rows, K cols])
__global__ void tsplit_tile(const float* __restrict__ W, char* __restrict__ dst,
                            int K, int Nn) {
    __shared__ float t[32][33];
    const int n0 = blockIdx.x * 32, k0 = blockIdx.y * 32;
    const int tx = threadIdx.x, ty = threadIdx.y;  // (32, 8)
    #pragma unroll
    for (int i = 0; i < 4; i++) {
        const int k = k0 + ty + i * 8;
        t[ty + i * 8][tx] = W[(size_t)k * Nn + n0 + tx];
    }
    __syncthreads();
    const int tid = ty * 32 + tx;
    const int nl = tid >> 3, kl = (tid & 7) << 2;
    uint32_t h0, l0, h1, l1;
    split_pack(t[kl][nl],     t[kl + 1][nl], h0, l0);
    split_pack(t[kl + 2][nl], t[kl + 3][nl], h1, l1);
    *reinterpret_cast<uint2*>(dst + utile_off(n0 + nl, k0 + kl, K, 0)) = make_uint2(h0, h1);
    *reinterpret_cast<uint2*>(dst + utile_off(n0 + nl, k0 + kl, K, 1)) = make_uint2(l0, l1);
}

// ---------------------------------------------------------------------------
// Shared GEMM mainloop: 3-stage bulk pipeline, ldmatrix fragment loads.
// ---------------------------------------------------------------------------
__device__ __forceinline__ void gemm_mainloop(
    uint32_t sb, int tid, int wid, int lane,
    const char* Ahl, const char* Bhl,
    size_t tbA, size_t tbB, int Kc, float cfr[2][8][4])
{
    const int wm = wid & 3, wn = wid >> 2;

    const uint32_t lA = (uint32_t)((lane & 7) + ((lane >> 3) & 1) * 8);
    const uint32_t cA = (uint32_t)(lane >> 4);
    const uint32_t lB = (uint32_t)((lane & 7) + (lane >> 4) * 8);
    const uint32_t cB = (uint32_t)((lane >> 3) & 1);

    auto produce = [&](int p) {
        const int s = p % 3;
        const uint32_t st = sb + 1024 + s * 32768;
        mbar_expect(sb + s * 8, 32768);
        bulk_g2s(st,         Ahl + (tbA + p) * 16384, 16384, sb + s * 8);
        bulk_g2s(st + 16384, Bhl + (tbB + p) * 16384, 16384, sb + s * 8);
    };

    if (tid == 0) { produce(0); produce(1); }

    for (int c = 0; c < Kc; c++) {
        const int cs = c % 3, cph = (c / 3) & 1;
        if (tid == 0) {
            const int p = c + 2;
            if (p < Kc) {
                const int ps = p % 3;
                if (p >= 3) mbar_wait(sb + 32 + ps * 8, (uint32_t)(((p / 3) - 1) & 1));
                produce(p);
            }
        }
        mbar_wait(sb + cs * 8, (uint32_t)cph);

        const uint32_t st = sb + 1024 + cs * 32768;
        #pragma unroll
        for (int ks = 0; ks < 2; ks++) {
            uint32_t ah[2][4], al[2][4];
            #pragma unroll
            for (int mt = 0; mt < 2; mt++) {
                const uint32_t row = (uint32_t)(wm * 32 + mt * 16) + lA;
                const uint32_t rb = st + row * 128;
                LDMX4(ah[mt][0], ah[mt][1], ah[mt][2], ah[mt][3],
                      rb + (((2 * ks + cA) ^ (row & 7)) << 4));
                LDMX4(al[mt][0], al[mt][1], al[mt][2], al[mt][3],
                      rb + (((2 * ks + cA + 4) ^ (row & 7)) << 4));
            }
            #pragma unroll
            for (int p = 0; p < 4; p++) {
                const uint32_t row = (uint32_t)(wn * 64 + p * 16) + lB;
                const uint32_t rb = st + 16384 + row * 128;
                uint32_t h0, h1, h2, h3, l0, l1, l2, l3;
                LDMX4(h0, h1, h2, h3, rb + (((2 * ks + cB) ^ (row & 7)) << 4));
                LDMX4(l0, l1, l2, l3, rb + (((2 * ks + cB + 4) ^ (row & 7)) << 4));
                uint32_t bh0[2] = {h0, h1}, bh1[2] = {h2, h3};
                uint32_t bl0[2] = {l0, l1}, bl1[2] = {l2, l3};
                #pragma unroll
                for (int mt = 0; mt < 2; mt++) {
                    mma16816(cfr[mt][2 * p],     ah[mt], bh0);
                    mma16816(cfr[mt][2 * p],     ah[mt], bl0);
                    mma16816(cfr[mt][2 * p],     al[mt], bh0);
                    mma16816(cfr[mt][2 * p + 1], ah[mt], bh1);
                    mma16816(cfr[mt][2 * p + 1], ah[mt], bl1);
                    mma16816(cfr[mt][2 * p + 1], al[mt], bh1);
                }
            }
        }
        mbar_arrive(sb + 32 + cs * 8);
    }
}

__device__ __forceinline__ void gemm_barrier_init(uint32_t sb, int tid) {
    if (tid == 0) {
        #pragma unroll
        for (int s = 0; s < 3; s++) {
            mbar_init(sb + s * 8, 1);
            mbar_init(sb + 32 + s * 8, 256);
        }
        asm volatile("fence.proxy.async.shared::cta;" ::: "memory");
    }
    __syncthreads();
}

// ---------------------------------------------------------------------------
// Generic HMMA GEMM (proj): fp32 epilogue + bias
// ---------------------------------------------------------------------------
__global__ __launch_bounds__(256, 2) void gemm_hmma(
    const char* __restrict__ Ahl, const char* __restrict__ Bhl,
    const float* __restrict__ bias, float* __restrict__ Cout,
    int M, int Nn, int K)
{
    extern __shared__ char smem[];
    const uint32_t sb = smem_u32(smem);
    const int tid = threadIdx.x, wid = tid >> 5, lane = tid & 31;
    const int gid = lane >> 2, tig = lane & 3;
    const int wm = wid & 3, wn = wid >> 2;
    const int Kc = K >> 5;

    gemm_barrier_init(sb, tid);

    float cfr[2][8][4];
    #pragma unroll
    for (int mt = 0; mt < 2; mt++)
        #pragma unroll
        for (int nt = 0; nt < 8; nt++)
            #pragma unroll
            for (int q = 0; q < 4; q++) cfr[mt][nt][q] = 0.f;

    gemm_mainloop(sb, tid, wid, lane, Ahl, Bhl,
                  (size_t)blockIdx.y * Kc, (size_t)blockIdx.x * Kc, Kc, cfr);

    const int m0 = blockIdx.y * 128, n0 = blockIdx.x * 128;
    #pragma unroll
    for (int mt = 0; mt < 2; mt++) {
        const int r = m0 + wm * 32 + mt * 16 + gid;
        #pragma unroll
        for (int nt = 0; nt < 8; nt++) {
            const int col = n0 + wn * 64 + nt * 8 + tig * 2;
            float b0 = bias ? bias[col] : 0.f;
            float b1 = bias ? bias[col + 1] : 0.f;
            *reinterpret_cast<float2*>(&Cout[(size_t)r * Nn + col]) =
                make_float2(cfr[mt][nt][0] + b0, cfr[mt][nt][1] + b1);
            *reinterpret_cast<float2*>(&Cout[(size_t)(r + 8) * Nn + col]) =
                make_float2(cfr[mt][nt][2] + b0, cfr[mt][nt][3] + b1);
        }
    }
}

// ---------------------------------------------------------------------------
// QKV GEMM with fused flash-tile epilogue (Q scaled by QSCALE).
// ---------------------------------------------------------------------------
__global__ __launch_bounds__(256, 2) void gemm_qkv(
    const char* __restrict__ Ahl, const char* __restrict__ Bhl,
    char* __restrict__ fq, char* __restrict__ fk, char* __restrict__ fv)
{
    extern __shared__ char smem[];
    const uint32_t sb = smem_u32(smem);
    const int tid = threadIdx.x, wid = tid >> 5, lane = tid & 31;
    const int gid = lane >> 2, tig = lane & 3;
    const int wm = wid & 3, wn = wid >> 2;
    constexpr int Kc = CDIM >> 5;  // 32

    gemm_barrier_init(sb, tid);

    float cfr[2][8][4];
    #pragma unroll
    for (int mt = 0; mt < 2; mt++)
        #pragma unroll
        for (int nt = 0; nt < 8; nt++)
            #pragma unroll
            for (int q = 0; q < 4; q++) cfr[mt][nt][q] = 0.f;

    gemm_mainloop(sb, tid, wid, lane, Ahl, Bhl,
                  (size_t)blockIdx.y * Kc, (size_t)blockIdx.x * Kc, Kc, cfr);

    const int b = blockIdx.y >> 4, tile = blockIdx.y & 15;
    const int bx = blockIdx.x;

    if (bx < 16) {
        const bool isQ = bx < 8;
        const int j = isQ ? bx : bx - 8;
        char* const fbase = isQ ? fq : fk;
        const float sc = isQ ? QSCALE : 1.0f;
        #pragma unroll
        for (int mt = 0; mt < 2; mt++) {
            const int rA = wm * 32 + mt * 16 + gid;
            #pragma unroll
            for (int nt = 0; nt < 8; nt++) {
                const int c = wn * 64 + nt * 8 + tig * 2;
                const int h = 2 * j + (c >> 6);
                const int d = c & 63;
                char* dst = fbase + (((size_t)b * NHEADS + h) * 16 + tile) * 32768;
                const int kc = d >> 5, chunk = (d & 31) >> 3, bo = (d & 7) * 2;
                uint32_t hi0, lo0, hi1, lo1;
                split_pack(cfr[mt][nt][0] * sc, cfr[mt][nt][1] * sc, hi0, lo0);
                split_pack(cfr[mt][nt][2] * sc, cfr[mt][nt][3] * sc, hi1, lo1);
                char* baseA = dst + kc * 16384 + rA * 128;
                char* baseB = dst + kc * 16384 + (rA + 8) * 128;
                *reinterpret_cast<uint32_t*>(baseA + (((chunk)     ^ (rA & 7)) << 4) + bo) = hi0;
                *reinterpret_cast<uint32_t*>(baseA + (((chunk + 4) ^ (rA & 7)) << 4) + bo) = lo0;
                *reinterpret_cast<uint32_t*>(baseB + (((chunk)     ^ ((rA + 8) & 7)) << 4) + bo) = hi1;
                *reinterpret_cast<uint32_t*>(baseB + (((chunk + 4) ^ ((rA + 8) & 7)) << 4) + bo) = lo1;
            }
        }
    } else {
        const int j = bx - 16;
        float* vs = reinterpret_cast<float*>(smem + 1024);
        constexpr int VST = 130;
        __syncthreads();
        #pragma unroll
        for (int mt = 0; mt < 2; mt++) {
            const int rA = wm * 32 + mt * 16 + gid;
            #pragma unroll
            for (int nt = 0; nt < 8; nt++) {
                const int c = wn * 64 + nt * 8 + tig * 2;
                vs[rA * VST + c]           = cfr[mt][nt][0];
                vs[rA * VST + c + 1]       = cfr[mt][nt][1];
                vs[(rA + 8) * VST + c]     = cfr[mt][nt][2];
                vs[(rA + 8) * VST + c + 1] = cfr[mt][nt][3];
            }
        }
        __syncthreads();
        for (int it = tid; it < 4096; it += 256) {
            const int hsel = it >> 11, rem = it & 2047;
            const int d = rem >> 5, k4 = (rem & 31) * 4;
            const int cc = hsel * 64 + d;
            float4 v = make_float4(vs[k4 * VST + cc], vs[(k4 + 1) * VST + cc],
                                   vs[(k4 + 2) * VST + cc], vs[(k4 + 3) * VST + cc]);
            uint32_t h0, l0, h1, l1;
            split_pack(v.x, v.y, h0, l0);
            split_pack(v.z, v.w, h1, l1);
            char* vdst = fv + (((size_t)b * NHEADS + 2 * j + hsel) * 16 + tile) * 32768;
            const int kc = k4 >> 5, chunk = (k4 & 31) >> 3, bo = (k4 & 7) * 2;
            char* base = vdst + kc * 8192 + d * 128;
            *reinterpret_cast<uint2*>(base + (((chunk)     ^ (d & 7)) << 4) + bo) =
                make_uint2(h0, h1);
            *reinterpret_cast<uint2*>(base + (((chunk + 4) ^ (d & 7)) << 4) + bo) =
                make_uint2(l0, l1);
        }
    }
}

// ---------------------------------------------------------------------------
// HMMA flash attention: 128-key tiles, 2-stage pipeline, 1 CTA/SM.
// Per-kc exp/repack interleaved with PV MMAs (R13 champion).
// ---------------------------------------------------------------------------
__global__ __launch_bounds__(256, 1) void flash_hmma(
    const char* __restrict__ fq, const char* __restrict__ fk,
    const char* __restrict__ fv, const int* __restrict__ mask,
    char* __restrict__ outt)
{
    extern __shared__ char smem[];
    const uint32_t sb = smem_u32(smem);
    const int tid = threadIdx.x, w = tid >> 5, lane = tid & 31;
    const int gid = lane >> 2, tig = lane & 3;
    const int qt = blockIdx.x, h = blockIdx.y, b = blockIdx.z;
    const size_t bh = (size_t)b * NHEADS + h;

    const uint32_t QS = sb + 1024;
    const uint32_t ST0 = QS + 32768;
    constexpr uint32_t STG = 66560;

    if (tid == 0) {
        mbar_init(sb + 0, 1);
        mbar_init(sb + 8, 1);  mbar_init(sb + 16, 1);
        mbar_init(sb + 24, 256); mbar_init(sb + 32, 256);
        asm volatile("fence.proxy.async.shared::cta;" ::: "memory");
    }
    __syncthreads();

    auto produce = [&](int kt) {
        const int s = kt & 1;
        const uint32_t st = ST0 + s * STG;
        mbar_expect(sb + 8 + s * 8, 65536 + 512);
        bulk_g2s(st,         fk + (bh * 16 + kt) * 32768, 32768, sb + 8 + s * 8);
        bulk_g2s(st + 32768, fv + (bh * 16 + kt) * 32768, 32768, sb + 8 + s * 8);
        bulk_g2s(st + 65536, (const char*)(mask + b * NDIM + kt * 128), 512, sb + 8 + s * 8);
    };

    if (tid == 0) {
        mbar_expect(sb + 0, 32768);
        bulk_g2s(QS, fq + (bh * 16 + qt) * 32768, 32768, sb + 0);
        produce(0); produce(1);
    }

    mbar_wait(sb + 0, 0);
    uint32_t qh[4][4], ql[4][4];
    {
        const uint32_t r0 = (uint32_t)(w * 16 + gid);
        #pragma unroll
        for (int ks = 0; ks < 4; ks++) {
            const uint32_t kc = ks >> 1, cb = 2 * (ks & 1);
            const uint32_t a0 = QS + kc * 16384 + tig * 4;
            const uint32_t rA = r0, rB = r0 + 8;
            qh[ks][0] = lds32(a0 + rA * 128 + (((cb)     ^ (rA & 7)) << 4));
            qh[ks][1] = lds32(a0 + rB * 128 + (((cb)     ^ (rB & 7)) << 4));
            qh[ks][2] = lds32(a0 + rA * 128 + (((cb + 1) ^ (rA & 7)) << 4));
            qh[ks][3] = lds32(a0 + rB * 128 + (((cb + 1) ^ (rB & 7)) << 4));
            ql[ks][0] = lds32(a0 + rA * 128 + (((cb + 4) ^ (rA & 7)) << 4));
            ql[ks][1] = lds32(a0 + rB * 128 + (((cb + 4) ^ (rB & 7)) << 4));
            ql[ks][2] = lds32(a0 + rA * 128 + (((cb + 5) ^ (rA & 7)) << 4));
            ql[ks][3] = lds32(a0 + rB * 128 + (((cb + 5) ^ (rB & 7)) << 4));
        }
    }

    float o[8][4];
    #pragma unroll
    for (int nt = 0; nt < 8; nt++)
        #pragma unroll
        for (int q = 0; q < 4; q++) o[nt][q] = 0.f;
    float mi0 = -1e30f, mi1 = -1e30f, li0 = 0.f, li1 = 0.f;

    const uint32_t lrow = (uint32_t)(lane & 7);
    const uint32_t lch = (uint32_t)(lane >> 3);

    #pragma unroll 1
    for (int kt = 0; kt < 16; kt++) {
        const int s = kt & 1;
        mbar_wait(sb + 8 + s * 8, (uint32_t)((kt >> 1) & 1));
        const uint32_t kbse = ST0 + s * STG;
        const uint32_t vbse = kbse + 32768;
        const uint32_t mbse = kbse + 65536;

        // ---- S = Q @ K^T (3-pass) ----
        float sf[16][4];
        #pragma unroll
        for (int j = 0; j < 16; j++) {
            sf[j][0] = sf[j][1] = sf[j][2] = sf[j][3] = 0.f;
            const uint32_t row = (uint32_t)(j * 8) + lrow;
            #pragma unroll
            for (int kc = 0; kc < 2; kc++) {
                const uint32_t rb = kbse + kc * 16384 + row * 128;
                uint32_t h0, h1, h2, h3, l0, l1, l2, l3;
                LDMX4(h0, h1, h2, h3, rb + (((lch)     ^ (row & 7)) << 4));
                LDMX4(l0, l1, l2, l3, rb + (((lch + 4) ^ (row & 7)) << 4));
                uint32_t bh0[2] = {h0, h1}, bh1[2] = {h2, h3};
                uint32_t bl0[2] = {l0, l1}, bl1[2] = {l2, l3};
                mma16816(sf[j], qh[2 * kc],     bh0);
                mma16816(sf[j], qh[2 * kc],     bl0);
                mma16816(sf[j], ql[2 * kc],     bh0);
                mma16816(sf[j], qh[2 * kc + 1], bh1);
                mma16816(sf[j], qh[2 * kc + 1], bl1);
                mma16816(sf[j], ql[2 * kc + 1], bh1);
            }
        }

        // ---- mask ----
        #pragma unroll
        for (int j = 0; j < 16; j++) {
            const uint32_t ma = mbse + (uint32_t)(j * 8 + 2 * tig) * 4;
            if ((int)lds32(ma) > 0)     { sf[j][0] = MASKVAL; sf[j][2] = MASKVAL; }
            if ((int)lds32(ma + 4) > 0) { sf[j][1] = MASKVAL; sf[j][3] = MASKVAL; }
        }

        // ---- max + rescale ----
        float rm0 = -1e30f, rm1 = -1e30f;
        #pragma unroll
        for (int j = 0; j < 16; j++) {
            rm0 = fmaxf(rm0, fmaxf(sf[j][0], sf[j][1]));
            rm1 = fmaxf(rm1, fmaxf(sf[j][2], sf[j][3]));
        }
        rm0 = fmaxf(rm0, __shfl_xor_sync(0xffffffffu, rm0, 1));
        rm0 = fmaxf(rm0, __shfl_xor_sync(0xffffffffu, rm0, 2));
        rm1 = fmaxf(rm1, __shfl_xor_sync(0xffffffffu, rm1, 1));
        rm1 = fmaxf(rm1, __shfl_xor_sync(0xffffffffu, rm1, 2));
        const float mn0 = fmaxf(mi0, rm0), mn1 = fmaxf(mi1, rm1);
        const float a0 = ex2f(mi0 - mn0), a1 = ex2f(mi1 - mn1);
        mi0 = mn0; mi1 = mn1;
        #pragma unroll
        for (int nt = 0; nt < 8; nt++) {
            o[nt][0] *= a0; o[nt][1] *= a0;
            o[nt][2] *= a1; o[nt][3] *= a1;
        }

        // ---- interleaved: per 32-key chunk, exp+repack then PV MMAs ----
        float rs0 = 0.f, rs1 = 0.f;
        #pragma unroll
        for (int kc = 0; kc < 4; kc++) {
            uint32_t pah[2][4], pal[2][4];
            #pragma unroll
            for (int jj = 0; jj < 2; jj++) {
                const int j0 = 4 * kc + 2 * jj;
                sf[j0][0] = ex2f(sf[j0][0] - mn0); rs0 += sf[j0][0];
                sf[j0][1] = ex2f(sf[j0][1] - mn0); rs0 += sf[j0][1];
                sf[j0][2] = ex2f(sf[j0][2] - mn1); rs1 += sf[j0][2];
                sf[j0][3] = ex2f(sf[j0][3] - mn1); rs1 += sf[j0][3];
                sf[j0 + 1][0] = ex2f(sf[j0 + 1][0] - mn0); rs0 += sf[j0 + 1][0];
                sf[j0 + 1][1] = ex2f(sf[j0 + 1][1] - mn0); rs0 += sf[j0 + 1][1];
                sf[j0 + 1][2] = ex2f(sf[j0 + 1][2] - mn1); rs1 += sf[j0 + 1][2];
                sf[j0 + 1][3] = ex2f(sf[j0 + 1][3] - mn1); rs1 += sf[j0 + 1][3];
                split_pack(sf[j0][0],     sf[j0][1],     pah[jj][0], pal[jj][0]);
                split_pack(sf[j0][2],     sf[j0][3],     pah[jj][1], pal[jj][1]);
                split_pack(sf[j0 + 1][0], sf[j0 + 1][1], pah[jj][2], pal[jj][2]);
                split_pack(sf[j0 + 1][2], sf[j0 + 1][3], pah[jj][3], pal[jj][3]);
            }
            #pragma unroll
            for (int nt = 0; nt < 8; nt++) {
                const uint32_t row = (uint32_t)(nt * 8) + lrow;
                const uint32_t rb = vbse + kc * 8192 + row * 128;
                uint32_t h0, h1, h2, h3, l0, l1, l2, l3;
                LDMX4(h0, h1, h2, h3, rb + (((lch)     ^ (row & 7)) << 4));
                LDMX4(l0, l1, l2, l3, rb + (((lch + 4) ^ (row & 7)) << 4));
                uint32_t vh0[2] = {h0, h1}, vh1[2] = {h2, h3};
                uint32_t vl0[2] = {l0, l1}, vl1[2] = {l2, l3};
                mma16816(o[nt], pah[0], vh0);
                mma16816(o[nt], pah[0], vl0);
                mma16816(o[nt], pal[0], vh0);
                mma16816(o[nt], pah[1], vh1);
                mma16816(o[nt], pah[1], vl1);
                mma16816(o[nt], pal[1], vh1);
            }
        }

        rs0 += __shfl_xor_sync(0xffffffffu, rs0, 1);
        rs0 += __shfl_xor_sync(0xffffffffu, rs0, 2);
        rs1 += __shfl_xor_sync(0xffffffffu, rs1, 1);
        rs1 += __shfl_xor_sync(0xffffffffu, rs1, 2);
        li0 = li0 * a0 + rs0;
        li1 = li1 * a1 + rs1;

        mbar_arrive(sb + 24 + s * 8);
        if (tid == 0 && kt + 2 < 16) {
            mbar_wait(sb + 24 + s * 8, (uint32_t)((kt >> 1) & 1));
            produce(kt + 2);
        }
    }

    // ---- epilogue: normalize, emit unified tiled bf16 (hi|lo) ----
    const float inv0 = 1.f / li0, inv1 = 1.f / li1;
    const int row0 = b * NDIM + qt * 128 + w * 16 + gid;
    #pragma unroll
    for (int nt = 0; nt < 8; nt++) {
        const int col = h * 64 + nt * 8 + tig * 2;
        uint32_t h0, l0, h1, l1;
        split_pack(o[nt][0] * inv0, o[nt][1] * inv0, h0, l0);
        split_pack(o[nt][2] * inv1, o[nt][3] * inv1, h1, l1);
        *reinterpret_cast<uint32_t*>(outt + utile_off(row0, col, CDIM, 0)) = h0;
        *reinterpret_cast<uint32_t*>(outt + utile_off(row0, col, CDIM, 1)) = l0;
        *reinterpret_cast<uint32_t*>(outt + utile_off(row0 + 8, col, CDIM, 0)) = h1;
        *reinterpret_cast<uint32_t*>(outt + utile_off(row0 + 8, col, CDIM, 1)) = l1;
    }
}

// ---------------------------------------------------------------------------
extern "C" void kernel_launch(void* const* d_in, const int* in_sizes, int n_in,
                              void* d_out, int out_size)
{
    const float* x     = (const float*)d_in[0];
    const float* Wqkv  = (const float*)d_in[1];
    const float* Wproj = (const float*)d_in[2];
    const float* bproj = (const float*)d_in[3];
    const int*   mask  = (const int*)d_in[4];
    float* out = (float*)d_out;

    const int B = BDIM, N = NDIM, C = CDIM, M = MROWS;

    char *x_p, *wq_p, *wp_p, *att_p, *fq_p, *fk_p, *fv_p;
    cudaGetSymbolAddress((void**)&x_p, g_x);
    cudaGetSymbolAddress((void**)&wq_p, g_wq);
    cudaGetSymbolAddress((void**)&wp_p, g_wp);
    cudaGetSymbolAddress((void**)&att_p, g_att);
    cudaGetSymbolAddress((void**)&fq_p, g_fq);
    cudaGetSymbolAddress((void**)&fk_p, g_fk);
    cudaGetSymbolAddress((void**)&fv_p, g_fv);

    // Prep
    const int n4 = M * C / 4;
    split_tile<<<(n4 + 255) / 256, 256>>>((const float4*)x, x_p, C, n4);
    tsplit_tile<<<dim3(3 * C / 32, C / 32), dim3(32, 8)>>>(Wqkv, wq_p, C, 3 * C);
    tsplit_tile<<<dim3(C / 32, C / 32), dim3(32, 8)>>>(Wproj, wp_p, C, C);

    const int gsmem = 1024 + 3 * 32768;
    cudaFuncSetAttribute(gemm_qkv, cudaFuncAttributeMaxDynamicSharedMemorySize, gsmem);
    cudaFuncSetAttribute(gemm_hmma, cudaFuncAttributeMaxDynamicSharedMemorySize, gsmem);

    // 1) QKV GEMM with fused flash-tile epilogue
    gemm_qkv<<<dim3(3 * C / 128, M / 128), 256, gsmem>>>(
        x_p, wq_p, fq_p, fk_p, fv_p);

    // 2) Flash attention (HMMA, ex2 softmax, 128-key tiles, 2-stage pipeline)
    const int fsmem = 1024 + 32768 + 2 * 66560;
    cudaFuncSetAttribute(flash_hmma, cudaFuncAttributeMaxDynamicSharedMemorySize, fsmem);
    flash_hmma<<<dim3(16, NHEADS, B), 256, fsmem>>>(
        fq_p, fk_p, fv_p, mask, att_p);

    // 3) Output projection
    gemm_hmma<<<dim3(C / 128, M / 128), 256, gsmem>>>(
        att_p, wp_p, bproj, out, M, C, C);
}

// round 16
// speedup vs baseline: 1.5938x; 1.0069x over previous
#include <cuda_runtime.h>
#include <cuda_bf16.h>
#include <cstdint>

#define NHEADS 16
#define DH 64
#define BDIM 4
#define NDIM 2048
#define CDIM 1024
#define MROWS (BDIM * NDIM)  // 8192

// ---------------- scratch (static; no runtime allocs) -----------------------
// Unified tile layout: [blk(128 rows)][kchunk(32 k)][row: 128B = hi 4x16B | lo 4x16B]
// 16B chunk swizzle: chunk' = chunk ^ (rowin & 7)  (ldmatrix-compatible).
__device__ char g_x[(MROWS / 128) * (CDIM / 32) * 16384];
__device__ char g_wq[(3 * CDIM / 128) * (CDIM / 32) * 16384];
__device__ char g_wp[(CDIM / 128) * (CDIM / 32) * 16384];
__device__ char g_att[(MROWS / 128) * (CDIM / 32) * 16384];
__device__ char g_fq[BDIM * NHEADS * 16 * 32768];
__device__ char g_fk[BDIM * NHEADS * 16 * 32768];
__device__ char g_fv[BDIM * NHEADS * 16 * 32768];

#define QSCALE 0.18033688011112042f   // Dh^-0.5 * log2(e)
#define MASKVAL -14426950.4f          // -1e7 * log2(e)

__device__ __forceinline__ size_t utile_off(int row, int k, int K, int hilo) {
    const int blk = row >> 7, rowin = row & 127;
    const int kc = k >> 5;
    const int chunk = ((k & 31) >> 3) + hilo * 4;
    return (size_t)(blk * (K >> 5) + kc) * 16384 + rowin * 128 +
           ((chunk ^ (rowin & 7)) << 4) + (k & 7) * 2;
}

// ---------------- PTX helpers ------------------------------------------------
__device__ __forceinline__ uint32_t smem_u32(const void* p) {
    uint32_t a;
    asm("{ .reg .u64 t; cvta.to.shared.u64 t, %1; cvt.u32.u64 %0, t; }"
        : "=r"(a) : "l"(p));
    return a;
}
__device__ __forceinline__ uint32_t lds32(uint32_t a) {
    uint32_t v;
    asm volatile("ld.shared.b32 %0, [%1];" : "=r"(v) : "r"(a));
    return v;
}
__device__ __forceinline__ float ex2f(float x) {
    float r;
    asm("ex2.approx.f32 %0, %1;" : "=f"(r) : "f"(x));
    return r;
}
__device__ __forceinline__ void mbar_init(uint32_t a, uint32_t cnt) {
    asm volatile("mbarrier.init.shared.b64 [%0], %1;" :: "r"(a), "r"(cnt) : "memory");
}
__device__ __forceinline__ void mbar_expect(uint32_t a, uint32_t bytes) {
    asm volatile("mbarrier.arrive.expect_tx.shared.b64 _, [%0], %1;"
                 :: "r"(a), "r"(bytes) : "memory");
}
__device__ __forceinline__ void mbar_arrive(uint32_t a) {
    asm volatile("mbarrier.arrive.shared.b64 _, [%0];" :: "r"(a) : "memory");
}
__device__ __forceinline__ void mbar_wait(uint32_t a, uint32_t parity) {
    asm volatile(
        "{\n\t.reg .pred P1;\n"
        "WAIT_LOOP_%=:\n\t"
        "mbarrier.try_wait.parity.acquire.cta.shared::cta.b64 P1, [%0], %1, 0x989680;\n\t"
        "@P1 bra.uni WAIT_DONE_%=;\n\t"
        "bra.uni WAIT_LOOP_%=;\n"
        "WAIT_DONE_%=:\n\t}"
        :: "r"(a), "r"(parity) : "memory");
}
__device__ __forceinline__ void bulk_g2s(uint32_t dst, const void* src,
                                         uint32_t bytes, uint32_t mbar) {
    asm volatile(
        "cp.async.bulk.shared::cluster.global.mbarrier::complete_tx::bytes "
        "[%0], [%1], %2, [%3];"
        :: "r"(dst), "l"(src), "r"(bytes), "r"(mbar) : "memory");
}
__device__ __forceinline__ void mma16816(float* c, const uint32_t* a,
                                         const uint32_t* b) {
    asm volatile(
        "mma.sync.aligned.m16n8k16.row.col.f32.bf16.bf16.f32 "
        "{%0,%1,%2,%3}, {%4,%5,%6,%7}, {%8,%9}, {%0,%1,%2,%3};"
        : "+f"(c[0]), "+f"(c[1]), "+f"(c[2]), "+f"(c[3])
        : "r"(a[0]), "r"(a[1]), "r"(a[2]), "r"(a[3]), "r"(b[0]), "r"(b[1]));
}
#define LDMX4(r0, r1, r2, r3, addr) \
    asm volatile("ldmatrix.sync.aligned.m8n8.x4.shared.b16 {%0,%1,%2,%3}, [%4];" \
                 : "=r"(r0), "=r"(r1), "=r"(r2), "=r"(r3) : "r"(addr))

__device__ __forceinline__ void split_bf16(float v, __nv_bfloat16& h, __nv_bfloat16& l) {
    h = __float2bfloat16(v);
    l = __float2bfloat16(v - __bfloat162float(h));
}
__device__ __forceinline__ uint32_t b2u(__nv_bfloat162 v) {
    return *reinterpret_cast<uint32_t*>(&v);
}
__device__ __forceinline__ void split_pack(float a, float b, uint32_t& hi, uint32_t& lo) {
    __nv_bfloat162 h = __floats2bfloat162_rn(a, b);
    __nv_bfloat162 l = __floats2bfloat162_rn(a - __bfloat162float(h.x),
                                             b - __bfloat162float(h.y));
    hi = b2u(h); lo = b2u(l);
}

// ---------------------------------------------------------------------------
// Fused prep: one launch, three roles (all independent).
//  bid in [0, 8192):           x fp32 -> unified tiled bf16 (split role)
//  bid in [8192, 8192+3072):   Wqkv^T tsplit role (Nn=3072)
//  bid in [11264, 11264+1024): Wproj^T tsplit role (Nn=1024)
// Per-role math and order identical to the previous separate kernels.
// ---------------------------------------------------------------------------
#define PREP_X_BLOCKS 8192
#define PREP_WQ_BLOCKS 3072
#define PREP_WP_BLOCKS 1024

__global__ __launch_bounds__(256) void prep_all(
    const float4* __restrict__ x, char* __restrict__ xd,
    const float* __restrict__ Wq, char* __restrict__ wqd,
    const float* __restrict__ Wp, char* __restrict__ wpd)
{
    const int bid = blockIdx.x;
    const int tid = threadIdx.x;

    if (bid < PREP_X_BLOCKS) {
        // ---- split role: x [M, C] fp32 -> tiled ----
        const int K = CDIM;
        const int i = bid * 256 + tid;
        const int n4 = MROWS * CDIM / 4;
        if (i >= n4) return;
        const int K4 = K >> 2;
        const int row = i / K4, k = (i % K4) << 2;
        float4 v = x[i];
        uint32_t h0, l0, h1, l1;
        split_pack(v.x, v.y, h0, l0);
        split_pack(v.z, v.w, h1, l1);
        *reinterpret_cast<uint2*>(xd + utile_off(row, k, K, 0)) = make_uint2(h0, h1);
        *reinterpret_cast<uint2*>(xd + utile_off(row, k, K, 1)) = make_uint2(l0, l1);
        return;
    }

    // ---- tsplit role ----
    const float* W;
    char* dst;
    int Nn, bx, by;
    if (bid < PREP_X_BLOCKS + PREP_WQ_BLOCKS) {
        const int idx = bid - PREP_X_BLOCKS;
        W = Wq; dst = wqd; Nn = 3 * CDIM;
        bx = idx % (3 * CDIM / 32);  // 96
        by = idx / (3 * CDIM / 32);
    } else {
        const int idx = bid - PREP_X_BLOCKS - PREP_WQ_BLOCKS;
        W = Wp; dst = wpd; Nn = CDIM;
        bx = idx % (CDIM / 32);      // 32
        by = idx / (CDIM / 32);
    }
    const int K = CDIM;

    __shared__ float t[32][33];
    const int n0 = bx * 32, k0 = by * 32;
    const int tx = tid & 31, ty = tid >> 5;  // (32, 8)
    #pragma unroll
    for (int i = 0; i < 4; i++) {
        const int k = k0 + ty + i * 8;
        t[ty + i * 8][tx] = W[(size_t)k * Nn + n0 + tx];
    }
    __syncthreads();
    const int nl = tid >> 3, kl = (tid & 7) << 2;
    uint32_t h0, l0, h1, l1;
    split_pack(t[kl][nl],     t[kl + 1][nl], h0, l0);
    split_pack(t[kl + 2][nl], t[kl + 3][nl], h1, l1);
    *reinterpret_cast<uint2*>(dst + utile_off(n0 + nl, k0 + kl, K, 0)) = make_uint2(h0, h1);
    *reinterpret_cast<uint2*>(dst + utile_off(n0 + nl, k0 + kl, K, 1)) = make_uint2(l0, l1);
}

// ---------------------------------------------------------------------------
// Shared GEMM mainloop: 3-stage bulk pipeline, ldmatrix fragment loads.
// ---------------------------------------------------------------------------
__device__ __forceinline__ void gemm_mainloop(
    uint32_t sb, int tid, int wid, int lane,
    const char* Ahl, const char* Bhl,
    size_t tbA, size_t tbB, int Kc, float cfr[2][8][4])
{
    const int wm = wid & 3, wn = wid >> 2;

    const uint32_t lA = (uint32_t)((lane & 7) + ((lane >> 3) & 1) * 8);
    const uint32_t cA = (uint32_t)(lane >> 4);
    const uint32_t lB = (uint32_t)((lane & 7) + (lane >> 4) * 8);
    const uint32_t cB = (uint32_t)((lane >> 3) & 1);

    auto produce = [&](int p) {
        const int s = p % 3;
        const uint32_t st = sb + 1024 + s * 32768;
        mbar_expect(sb + s * 8, 32768);
        bulk_g2s(st,         Ahl + (tbA + p) * 16384, 16384, sb + s * 8);
        bulk_g2s(st + 16384, Bhl + (tbB + p) * 16384, 16384, sb + s * 8);
    };

    if (tid == 0) { produce(0); produce(1); }

    for (int c = 0; c < Kc; c++) {
        const int cs = c % 3, cph = (c / 3) & 1;
        if (tid == 0) {
            const int p = c + 2;
            if (p < Kc) {
                const int ps = p % 3;
                if (p >= 3) mbar_wait(sb + 32 + ps * 8, (uint32_t)(((p / 3) - 1) & 1));
                produce(p);
            }
        }
        mbar_wait(sb + cs * 8, (uint32_t)cph);

        const uint32_t st = sb + 1024 + cs * 32768;
        #pragma unroll
        for (int ks = 0; ks < 2; ks++) {
            uint32_t ah[2][4], al[2][4];
            #pragma unroll
            for (int mt = 0; mt < 2; mt++) {
                const uint32_t row = (uint32_t)(wm * 32 + mt * 16) + lA;
                const uint32_t rb = st + row * 128;
                LDMX4(ah[mt][0], ah[mt][1], ah[mt][2], ah[mt][3],
                      rb + (((2 * ks + cA) ^ (row & 7)) << 4));
                LDMX4(al[mt][0], al[mt][1], al[mt][2], al[mt][3],
                      rb + (((2 * ks + cA + 4) ^ (row & 7)) << 4));
            }
            #pragma unroll
            for (int p = 0; p < 4; p++) {
                const uint32_t row = (uint32_t)(wn * 64 + p * 16) + lB;
                const uint32_t rb = st + 16384 + row * 128;
                uint32_t h0, h1, h2, h3, l0, l1, l2, l3;
                LDMX4(h0, h1, h2, h3, rb + (((2 * ks + cB) ^ (row & 7)) << 4));
                LDMX4(l0, l1, l2, l3, rb + (((2 * ks + cB + 4) ^ (row & 7)) << 4));
                uint32_t bh0[2] = {h0, h1}, bh1[2] = {h2, h3};
                uint32_t bl0[2] = {l0, l1}, bl1[2] = {l2, l3};
                #pragma unroll
                for (int mt = 0; mt < 2; mt++) {
                    mma16816(cfr[mt][2 * p],     ah[mt], bh0);
                    mma16816(cfr[mt][2 * p],     ah[mt], bl0);
                    mma16816(cfr[mt][2 * p],     al[mt], bh0);
                    mma16816(cfr[mt][2 * p + 1], ah[mt], bh1);
                    mma16816(cfr[mt][2 * p + 1], ah[mt], bl1);
                    mma16816(cfr[mt][2 * p + 1], al[mt], bh1);
                }
            }
        }
        mbar_arrive(sb + 32 + cs * 8);
    }
}

__device__ __forceinline__ void gemm_barrier_init(uint32_t sb, int tid) {
    if (tid == 0) {
        #pragma unroll
        for (int s = 0; s < 3; s++) {
            mbar_init(sb + s * 8, 1);
            mbar_init(sb + 32 + s * 8, 256);
        }
        asm volatile("fence.proxy.async.shared::cta;" ::: "memory");
    }
    __syncthreads();
}

// ---------------------------------------------------------------------------
// Generic HMMA GEMM (proj): fp32 epilogue + bias
// ---------------------------------------------------------------------------
__global__ __launch_bounds__(256, 2) void gemm_hmma(
    const char* __restrict__ Ahl, const char* __restrict__ Bhl,
    const float* __restrict__ bias, float* __restrict__ Cout,
    int M, int Nn, int K)
{
    extern __shared__ char smem[];
    const uint32_t sb = smem_u32(smem);
    const int tid = threadIdx.x, wid = tid >> 5, lane = tid & 31;
    const int gid = lane >> 2, tig = lane & 3;
    const int wm = wid & 3, wn = wid >> 2;
    const int Kc = K >> 5;

    gemm_barrier_init(sb, tid);

    float cfr[2][8][4];
    #pragma unroll
    for (int mt = 0; mt < 2; mt++)
        #pragma unroll
        for (int nt = 0; nt < 8; nt++)
            #pragma unroll
            for (int q = 0; q < 4; q++) cfr[mt][nt][q] = 0.f;

    gemm_mainloop(sb, tid, wid, lane, Ahl, Bhl,
                  (size_t)blockIdx.y * Kc, (size_t)blockIdx.x * Kc, Kc, cfr);

    const int m0 = blockIdx.y * 128, n0 = blockIdx.x * 128;
    #pragma unroll
    for (int mt = 0; mt < 2; mt++) {
        const int r = m0 + wm * 32 + mt * 16 + gid;
        #pragma unroll
        for (int nt = 0; nt < 8; nt++) {
            const int col = n0 + wn * 64 + nt * 8 + tig * 2;
            float b0 = bias ? bias[col] : 0.f;
            float b1 = bias ? bias[col + 1] : 0.f;
            *reinterpret_cast<float2*>(&Cout[(size_t)r * Nn + col]) =
                make_float2(cfr[mt][nt][0] + b0, cfr[mt][nt][1] + b1);
            *reinterpret_cast<float2*>(&Cout[(size_t)(r + 8) * Nn + col]) =
                make_float2(cfr[mt][nt][2] + b0, cfr[mt][nt][3] + b1);
        }
    }
}

// ---------------------------------------------------------------------------
// QKV GEMM with fused flash-tile epilogue (Q scaled by QSCALE).
// ---------------------------------------------------------------------------
__global__ __launch_bounds__(256, 2) void gemm_qkv(
    const char* __restrict__ Ahl, const char* __restrict__ Bhl,
    char* __restrict__ fq, char* __restrict__ fk, char* __restrict__ fv)
{
    extern __shared__ char smem[];
    const uint32_t sb = smem_u32(smem);
    const int tid = threadIdx.x, wid = tid >> 5, lane = tid & 31;
    const int gid = lane >> 2, tig = lane & 3;
    const int wm = wid & 3, wn = wid >> 2;
    constexpr int Kc = CDIM >> 5;  // 32

    gemm_barrier_init(sb, tid);

    float cfr[2][8][4];
    #pragma unroll
    for (int mt = 0; mt < 2; mt++)
        #pragma unroll
        for (int nt = 0; nt < 8; nt++)
            #pragma unroll
            for (int q = 0; q < 4; q++) cfr[mt][nt][q] = 0.f;

    gemm_mainloop(sb, tid, wid, lane, Ahl, Bhl,
                  (size_t)blockIdx.y * Kc, (size_t)blockIdx.x * Kc, Kc, cfr);

    const int b = blockIdx.y >> 4, tile = blockIdx.y & 15;
    const int bx = blockIdx.x;

    if (bx < 16) {
        const bool isQ = bx < 8;
        const int j = isQ ? bx : bx - 8;
        char* const fbase = isQ ? fq : fk;
        const float sc = isQ ? QSCALE : 1.0f;
        #pragma unroll
        for (int mt = 0; mt < 2; mt++) {
            const int rA = wm * 32 + mt * 16 + gid;
            #pragma unroll
            for (int nt = 0; nt < 8; nt++) {
                const int c = wn * 64 + nt * 8 + tig * 2;
                const int h = 2 * j + (c >> 6);
                const int d = c & 63;
                char* dst = fbase + (((size_t)b * NHEADS + h) * 16 + tile) * 32768;
                const int kc = d >> 5, chunk = (d & 31) >> 3, bo = (d & 7) * 2;
                uint32_t hi0, lo0, hi1, lo1;
                split_pack(cfr[mt][nt][0] * sc, cfr[mt][nt][1] * sc, hi0, lo0);
                split_pack(cfr[mt][nt][2] * sc, cfr[mt][nt][3] * sc, hi1, lo1);
                char* baseA = dst + kc * 16384 + rA * 128;
                char* baseB = dst + kc * 16384 + (rA + 8) * 128;
                *reinterpret_cast<uint32_t*>(baseA + (((chunk)     ^ (rA & 7)) << 4) + bo) = hi0;
                *reinterpret_cast<uint32_t*>(baseA + (((chunk + 4) ^ (rA & 7)) << 4) + bo) = lo0;
                *reinterpret_cast<uint32_t*>(baseB + (((chunk)     ^ ((rA + 8) & 7)) << 4) + bo) = hi1;
                *reinterpret_cast<uint32_t*>(baseB + (((chunk + 4) ^ ((rA + 8) & 7)) << 4) + bo) = lo1;
            }
        }
    } else {
        const int j = bx - 16;
        float* vs = reinterpret_cast<float*>(smem + 1024);
        constexpr int VST = 130;
        __syncthreads();
        #pragma unroll
        for (int mt = 0; mt < 2; mt++) {
            const int rA = wm * 32 + mt * 16 + gid;
            #pragma unroll
            for (int nt = 0; nt < 8; nt++) {
                const int c = wn * 64 + nt * 8 + tig * 2;
                vs[rA * VST + c]           = cfr[mt][nt][0];
                vs[rA * VST + c + 1]       = cfr[mt][nt][1];
                vs[(rA + 8) * VST + c]     = cfr[mt][nt][2];
                vs[(rA + 8) * VST + c + 1] = cfr[mt][nt][3];
            }
        }
        __syncthreads();
        for (int it = tid; it < 4096; it += 256) {
            const int hsel = it >> 11, rem = it & 2047;
            const int d = rem >> 5, k4 = (rem & 31) * 4;
            const int cc = hsel * 64 + d;
            float4 v = make_float4(vs[k4 * VST + cc], vs[(k4 + 1) * VST + cc],
                                   vs[(k4 + 2) * VST + cc], vs[(k4 + 3) * VST + cc]);
            uint32_t h0, l0, h1, l1;
            split_pack(v.x, v.y, h0, l0);
            split_pack(v.z, v.w, h1, l1);
            char* vdst = fv + (((size_t)b * NHEADS + 2 * j + hsel) * 16 + tile) * 32768;
            const int kc = k4 >> 5, chunk = (k4 & 31) >> 3, bo = (k4 & 7) * 2;
            char* base = vdst + kc * 8192 + d * 128;
            *reinterpret_cast<uint2*>(base + (((chunk)     ^ (d & 7)) << 4) + bo) =
                make_uint2(h0, h1);
            *reinterpret_cast<uint2*>(base + (((chunk + 4) ^ (d & 7)) << 4) + bo) =
                make_uint2(l0, l1);
        }
    }
}

// ---------------------------------------------------------------------------
// HMMA flash attention: 128-key tiles, 2-stage pipeline, 1 CTA/SM.
// Per-kc exp/repack interleaved with PV MMAs (R13/R15 champion).
// ---------------------------------------------------------------------------
__global__ __launch_bounds__(256, 1) void flash_hmma(
    const char* __restrict__ fq, const char* __restrict__ fk,
    const char* __restrict__ fv, const int* __restrict__ mask,
    char* __restrict__ outt)
{
    extern __shared__ char smem[];
    const uint32_t sb = smem_u32(smem);
    const int tid = threadIdx.x, w = tid >> 5, lane = tid & 31;
    const int gid = lane >> 2, tig = lane & 3;
    const int qt = blockIdx.x, h = blockIdx.y, b = blockIdx.z;
    const size_t bh = (size_t)b * NHEADS + h;

    const uint32_t QS = sb + 1024;
    const uint32_t ST0 = QS + 32768;
    constexpr uint32_t STG = 66560;

    if (tid == 0) {
        mbar_init(sb + 0, 1);
        mbar_init(sb + 8, 1);  mbar_init(sb + 16, 1);
        mbar_init(sb + 24, 256); mbar_init(sb + 32, 256);
        asm volatile("fence.proxy.async.shared::cta;" ::: "memory");
    }
    __syncthreads();

    auto produce = [&](int kt) {
        const int s = kt & 1;
        const uint32_t st = ST0 + s * STG;
        mbar_expect(sb + 8 + s * 8, 65536 + 512);
        bulk_g2s(st,         fk + (bh * 16 + kt) * 32768, 32768, sb + 8 + s * 8);
        bulk_g2s(st + 32768, fv + (bh * 16 + kt) * 32768, 32768, sb + 8 + s * 8);
        bulk_g2s(st + 65536, (const char*)(mask + b * NDIM + kt * 128), 512, sb + 8 + s * 8);
    };

    if (tid == 0) {
        mbar_expect(sb + 0, 32768);
        bulk_g2s(QS, fq + (bh * 16 + qt) * 32768, 32768, sb + 0);
        produce(0); produce(1);
    }

    mbar_wait(sb + 0, 0);
    uint32_t qh[4][4], ql[4][4];
    {
        const uint32_t r0 = (uint32_t)(w * 16 + gid);
        #pragma unroll
        for (int ks = 0; ks < 4; ks++) {
            const uint32_t kc = ks >> 1, cb = 2 * (ks & 1);
            const uint32_t a0 = QS + kc * 16384 + tig * 4;
            const uint32_t rA = r0, rB = r0 + 8;
            qh[ks][0] = lds32(a0 + rA * 128 + (((cb)     ^ (rA & 7)) << 4));
            qh[ks][1] = lds32(a0 + rB * 128 + (((cb)     ^ (rB & 7)) << 4));
            qh[ks][2] = lds32(a0 + rA * 128 + (((cb + 1) ^ (rA & 7)) << 4));
            qh[ks][3] = lds32(a0 + rB * 128 + (((cb + 1) ^ (rB & 7)) << 4));
            ql[ks][0] = lds32(a0 + rA * 128 + (((cb + 4) ^ (rA & 7)) << 4));
            ql[ks][1] = lds32(a0 + rB * 128 + (((cb + 4) ^ (rB & 7)) << 4));
            ql[ks][2] = lds32(a0 + rA * 128 + (((cb + 5) ^ (rA & 7)) << 4));
            ql[ks][3] = lds32(a0 + rB * 128 + (((cb + 5) ^ (rB & 7)) << 4));
        }
    }

    float o[8][4];
    #pragma unroll
    for (int nt = 0; nt < 8; nt++)
        #pragma unroll
        for (int q = 0; q < 4; q++) o[nt][q] = 0.f;
    float mi0 = -1e30f, mi1 = -1e30f, li0 = 0.f, li1 = 0.f;

    const uint32_t lrow = (uint32_t)(lane & 7);
    const uint32_t lch = (uint32_t)(lane >> 3);

    #pragma unroll 1
    for (int kt = 0; kt < 16; kt++) {
        const int s = kt & 1;
        mbar_wait(sb + 8 + s * 8, (uint32_t)((kt >> 1) & 1));
        const uint32_t kbse = ST0 + s * STG;
        const uint32_t vbse = kbse + 32768;
        const uint32_t mbse = kbse + 65536;

        // ---- S = Q @ K^T (3-pass) ----
        float sf[16][4];
        #pragma unroll
        for (int j = 0; j < 16; j++) {
            sf[j][0] = sf[j][1] = sf[j][2] = sf[j][3] = 0.f;
            const uint32_t row = (uint32_t)(j * 8) + lrow;
            #pragma unroll
            for (int kc = 0; kc < 2; kc++) {
                const uint32_t rb = kbse + kc * 16384 + row * 128;
                uint32_t h0, h1, h2, h3, l0, l1, l2, l3;
                LDMX4(h0, h1, h2, h3, rb + (((lch)     ^ (row & 7)) << 4));
                LDMX4(l0, l1, l2, l3, rb + (((lch + 4) ^ (row & 7)) << 4));
                uint32_t bh0[2] = {h0, h1}, bh1[2] = {h2, h3};
                uint32_t bl0[2] = {l0, l1}, bl1[2] = {l2, l3};
                mma16816(sf[j], qh[2 * kc],     bh0);
                mma16816(sf[j], qh[2 * kc],     bl0);
                mma16816(sf[j], ql[2 * kc],     bh0);
                mma16816(sf[j], qh[2 * kc + 1], bh1);
                mma16816(sf[j], qh[2 * kc + 1], bl1);
                mma16816(sf[j], ql[2 * kc + 1], bh1);
            }
        }

        // ---- mask ----
        #pragma unroll
        for (int j = 0; j < 16; j++) {
            const uint32_t ma = mbse + (uint32_t)(j * 8 + 2 * tig) * 4;
            if ((int)lds32(ma) > 0)     { sf[j][0] = MASKVAL; sf[j][2] = MASKVAL; }
            if ((int)lds32(ma + 4) > 0) { sf[j][1] = MASKVAL; sf[j][3] = MASKVAL; }
        }

        // ---- max + rescale ----
        float rm0 = -1e30f, rm1 = -1e30f;
        #pragma unroll
        for (int j = 0; j < 16; j++) {
            rm0 = fmaxf(rm0, fmaxf(sf[j][0], sf[j][1]));
            rm1 = fmaxf(rm1, fmaxf(sf[j][2], sf[j][3]));
        }
        rm0 = fmaxf(rm0, __shfl_xor_sync(0xffffffffu, rm0, 1));
        rm0 = fmaxf(rm0, __shfl_xor_sync(0xffffffffu, rm0, 2));
        rm1 = fmaxf(rm1, __shfl_xor_sync(0xffffffffu, rm1, 1));
        rm1 = fmaxf(rm1, __shfl_xor_sync(0xffffffffu, rm1, 2));
        const float mn0 = fmaxf(mi0, rm0), mn1 = fmaxf(mi1, rm1);
        const float a0 = ex2f(mi0 - mn0), a1 = ex2f(mi1 - mn1);
        mi0 = mn0; mi1 = mn1;
        #pragma unroll
        for (int nt = 0; nt < 8; nt++) {
            o[nt][0] *= a0; o[nt][1] *= a0;
            o[nt][2] *= a1; o[nt][3] *= a1;
        }

        // ---- interleaved: per 32-key chunk, exp+repack then PV MMAs ----
        float rs0 = 0.f, rs1 = 0.f;
        #pragma unroll
        for (int kc = 0; kc < 4; kc++) {
            uint32_t pah[2][4], pal[2][4];
            #pragma unroll
            for (int jj = 0; jj < 2; jj++) {
                const int j0 = 4 * kc + 2 * jj;
                sf[j0][0] = ex2f(sf[j0][0] - mn0); rs0 += sf[j0][0];
                sf[j0][1] = ex2f(sf[j0][1] - mn0); rs0 += sf[j0][1];
                sf[j0][2] = ex2f(sf[j0][2] - mn1); rs1 += sf[j0][2];
                sf[j0][3] = ex2f(sf[j0][3] - mn1); rs1 += sf[j0][3];
                sf[j0 + 1][0] = ex2f(sf[j0 + 1][0] - mn0); rs0 += sf[j0 + 1][0];
                sf[j0 + 1][1] = ex2f(sf[j0 + 1][1] - mn0); rs0 += sf[j0 + 1][1];
                sf[j0 + 1][2] = ex2f(sf[j0 + 1][2] - mn1); rs1 += sf[j0 + 1][2];
                sf[j0 + 1][3] = ex2f(sf[j0 + 1][3] - mn1); rs1 += sf[j0 + 1][3];
                split_pack(sf[j0][0],     sf[j0][1],     pah[jj][0], pal[jj][0]);
                split_pack(sf[j0][2],     sf[j0][3],     pah[jj][1], pal[jj][1]);
                split_pack(sf[j0 + 1][0], sf[j0 + 1][1], pah[jj][2], pal[jj][2]);
                split_pack(sf[j0 + 1][2], sf[j0 + 1][3], pah[jj][3], pal[jj][3]);
            }
            #pragma unroll
            for (int nt = 0; nt < 8; nt++) {
                const uint32_t row = (uint32_t)(nt * 8) + lrow;
                const uint32_t rb = vbse + kc * 8192 + row * 128;
                uint32_t h0, h1, h2, h3, l0, l1, l2, l3;
                LDMX4(h0, h1, h2, h3, rb + (((lch)     ^ (row & 7)) << 4));
                LDMX4(l0, l1, l2, l3, rb + (((lch + 4) ^ (row & 7)) << 4));
                uint32_t vh0[2] = {h0, h1}, vh1[2] = {h2, h3};
                uint32_t vl0[2] = {l0, l1}, vl1[2] = {l2, l3};
                mma16816(o[nt], pah[0], vh0);
                mma16816(o[nt], pah[0], vl0);
                mma16816(o[nt], pal[0], vh0);
                mma16816(o[nt], pah[1], vh1);
                mma16816(o[nt], pah[1], vl1);
                mma16816(o[nt], pal[1], vh1);
            }
        }

        rs0 += __shfl_xor_sync(0xffffffffu, rs0, 1);
        rs0 += __shfl_xor_sync(0xffffffffu, rs0, 2);
        rs1 += __shfl_xor_sync(0xffffffffu, rs1, 1);
        rs1 += __shfl_xor_sync(0xffffffffu, rs1, 2);
        li0 = li0 * a0 + rs0;
        li1 = li1 * a1 + rs1;

        mbar_arrive(sb + 24 + s * 8);
        if (tid == 0 && kt + 2 < 16) {
            mbar_wait(sb + 24 + s * 8, (uint32_t)((kt >> 1) & 1));
            produce(kt + 2);
        }
    }

    // ---- epilogue: normalize, emit unified tiled bf16 (hi|lo) ----
    const float inv0 = 1.f / li0, inv1 = 1.f / li1;
    const int row0 = b * NDIM + qt * 128 + w * 16 + gid;
    #pragma unroll
    for (int nt = 0; nt < 8; nt++) {
        const int col = h * 64 + nt * 8 + tig * 2;
        uint32_t h0, l0, h1, l1;
        split_pack(o[nt][0] * inv0, o[nt][1] * inv0, h0, l0);
        split_pack(o[nt][2] * inv1, o[nt][3] * inv1, h1, l1);
        *reinterpret_cast<uint32_t*>(outt + utile_off(row0, col, CDIM, 0)) = h0;
        *reinterpret_cast<uint32_t*>(outt + utile_off(row0, col, CDIM, 1)) = l0;
        *reinterpret_cast<uint32_t*>(outt + utile_off(row0 + 8, col, CDIM, 0)) = h1;
        *reinterpret_cast<uint32_t*>(outt + utile_off(row0 + 8, col, CDIM, 1)) = l1;
    }
}

// ---------------------------------------------------------------------------
extern "C" void kernel_launch(void* const* d_in, const int* in_sizes, int n_in,
                              void* d_out, int out_size)
{
    const float* x     = (const float*)d_in[0];
    const float* Wqkv  = (const float*)d_in[1];
    const float* Wproj = (const float*)d_in[2];
    const float* bproj = (const float*)d_in[3];
    const int*   mask  = (const int*)d_in[4];
    float* out = (float*)d_out;

    const int B = BDIM, N = NDIM, C = CDIM, M = MROWS;

    char *x_p, *wq_p, *wp_p, *att_p, *fq_p, *fk_p, *fv_p;
    cudaGetSymbolAddress((void**)&x_p, g_x);
    cudaGetSymbolAddress((void**)&wq_p, g_wq);
    cudaGetSymbolAddress((void**)&wp_p, g_wp);
    cudaGetSymbolAddress((void**)&att_p, g_att);
    cudaGetSymbolAddress((void**)&fq_p, g_fq);
    cudaGetSymbolAddress((void**)&fk_p, g_fk);
    cudaGetSymbolAddress((void**)&fv_p, g_fv);

    // 0) Fused prep (single launch; three independent roles)
    prep_all<<<PREP_X_BLOCKS + PREP_WQ_BLOCKS + PREP_WP_BLOCKS, 256>>>(
        (const float4*)x, x_p, Wqkv, wq_p, Wproj, wp_p);

    const int gsmem = 1024 + 3 * 32768;
    cudaFuncSetAttribute(gemm_qkv, cudaFuncAttributeMaxDynamicSharedMemorySize, gsmem);
    cudaFuncSetAttribute(gemm_hmma, cudaFuncAttributeMaxDynamicSharedMemorySize, gsmem);

    // 1) QKV GEMM with fused flash-tile epilogue
    gemm_qkv<<<dim3(3 * C / 128, M / 128), 256, gsmem>>>(
        x_p, wq_p, fq_p, fk_p, fv_p);

    // 2) Flash attention (HMMA, ex2 softmax, 128-key tiles, 2-stage pipeline)
    const int fsmem = 1024 + 32768 + 2 * 66560;
    cudaFuncSetAttribute(flash_hmma, cudaFuncAttributeMaxDynamicSharedMemorySize, fsmem);
    flash_hmma<<<dim3(16, NHEADS, B), 256, fsmem>>>(
        fq_p, fk_p, fv_p, mask, att_p);

    // 3) Output projection
    gemm_hmma<<<dim3(C / 128, M / 128), 256, gsmem>>>(
        att_p, wp_p, bproj, out, M, C, C);
}

// round 17
// speedup vs baseline: 1.6566x; 1.0394x over previous
#include <cuda_runtime.h>
#include <cuda_bf16.h>
#include <cuda_fp16.h>
#include <cstdint>

#define NHEADS 16
#define DH 64
#define BDIM 4
#define NDIM 2048
#define CDIM 1024
#define MROWS (BDIM * NDIM)  // 8192

// ---------------- scratch (static; no runtime allocs) -----------------------
// Unified tile layout (32k rows): [blk(128 rows)][kchunk(32 k)][row: 128B = hi 4x16B | lo 4x16B]
// 16B chunk swizzle: chunk' = chunk ^ (rowin & 7)  (ldmatrix-compatible).
__device__ char g_x[(MROWS / 128) * (CDIM / 32) * 16384];
__device__ char g_wq[(3 * CDIM / 128) * (CDIM / 32) * 16384];
// Wp: single-fp16 64k-per-row layout: [blk(128)][kc(64 k)][row: 128B = 8x16B chunks]
__device__ char g_wp[(CDIM / 128) * (CDIM / 64) * 16384];
__device__ char g_att[(MROWS / 128) * (CDIM / 32) * 16384];  // fp16 hi/lo
__device__ char g_fq[BDIM * NHEADS * 16 * 32768];
__device__ char g_fk[BDIM * NHEADS * 16 * 32768];
__device__ char g_fv[BDIM * NHEADS * 16 * 32768];

#define QSCALE 0.18033688011112042f   // Dh^-0.5 * log2(e)
#define MASKVAL -14426950.4f          // -1e7 * log2(e)

__device__ __forceinline__ size_t utile_off(int row, int k, int K, int hilo) {
    const int blk = row >> 7, rowin = row & 127;
    const int kc = k >> 5;
    const int chunk = ((k & 31) >> 3) + hilo * 4;
    return (size_t)(blk * (K >> 5) + kc) * 16384 + rowin * 128 +
           ((chunk ^ (rowin & 7)) << 4) + (k & 7) * 2;
}
// Wp 64k-per-row layout (K = 1024 fixed)
__device__ __forceinline__ size_t wtile_off(int row, int k) {
    const int blk = row >> 7, rowin = row & 127;
    const int kc = k >> 6;
    const int chunk = (k & 63) >> 3;
    return (size_t)(blk * (CDIM >> 6) + kc) * 16384 + rowin * 128 +
           ((chunk ^ (rowin & 7)) << 4) + (k & 7) * 2;
}

// ---------------- PTX helpers ------------------------------------------------
__device__ __forceinline__ uint32_t smem_u32(const void* p) {
    uint32_t a;
    asm("{ .reg .u64 t; cvta.to.shared.u64 t, %1; cvt.u32.u64 %0, t; }"
        : "=r"(a) : "l"(p));
    return a;
}
__device__ __forceinline__ uint32_t lds32(uint32_t a) {
    uint32_t v;
    asm volatile("ld.shared.b32 %0, [%1];" : "=r"(v) : "r"(a));
    return v;
}
__device__ __forceinline__ float ex2f(float x) {
    float r;
    asm("ex2.approx.f32 %0, %1;" : "=f"(r) : "f"(x));
    return r;
}
__device__ __forceinline__ void mbar_init(uint32_t a, uint32_t cnt) {
    asm volatile("mbarrier.init.shared.b64 [%0], %1;" :: "r"(a), "r"(cnt) : "memory");
}
__device__ __forceinline__ void mbar_expect(uint32_t a, uint32_t bytes) {
    asm volatile("mbarrier.arrive.expect_tx.shared.b64 _, [%0], %1;"
                 :: "r"(a), "r"(bytes) : "memory");
}
__device__ __forceinline__ void mbar_arrive(uint32_t a) {
    asm volatile("mbarrier.arrive.shared.b64 _, [%0];" :: "r"(a) : "memory");
}
__device__ __forceinline__ void mbar_wait(uint32_t a, uint32_t parity) {
    asm volatile(
        "{\n\t.reg .pred P1;\n"
        "WAIT_LOOP_%=:\n\t"
        "mbarrier.try_wait.parity.acquire.cta.shared::cta.b64 P1, [%0], %1, 0x989680;\n\t"
        "@P1 bra.uni WAIT_DONE_%=;\n\t"
        "bra.uni WAIT_LOOP_%=;\n"
        "WAIT_DONE_%=:\n\t}"
        :: "r"(a), "r"(parity) : "memory");
}
__device__ __forceinline__ void bulk_g2s(uint32_t dst, const void* src,
                                         uint32_t bytes, uint32_t mbar) {
    asm volatile(
        "cp.async.bulk.shared::cluster.global.mbarrier::complete_tx::bytes "
        "[%0], [%1], %2, [%3];"
        :: "r"(dst), "l"(src), "r"(bytes), "r"(mbar) : "memory");
}
__device__ __forceinline__ void mma16816(float* c, const uint32_t* a,
                                         const uint32_t* b) {
    asm volatile(
        "mma.sync.aligned.m16n8k16.row.col.f32.bf16.bf16.f32 "
        "{%0,%1,%2,%3}, {%4,%5,%6,%7}, {%8,%9}, {%0,%1,%2,%3};"
        : "+f"(c[0]), "+f"(c[1]), "+f"(c[2]), "+f"(c[3])
        : "r"(a[0]), "r"(a[1]), "r"(a[2]), "r"(a[3]), "r"(b[0]), "r"(b[1]));
}
__device__ __forceinline__ void mma16816h(float* c, const uint32_t* a,
                                          const uint32_t* b) {
    asm volatile(
        "mma.sync.aligned.m16n8k16.row.col.f32.f16.f16.f32 "
        "{%0,%1,%2,%3}, {%4,%5,%6,%7}, {%8,%9}, {%0,%1,%2,%3};"
        : "+f"(c[0]), "+f"(c[1]), "+f"(c[2]), "+f"(c[3])
        : "r"(a[0]), "r"(a[1]), "r"(a[2]), "r"(a[3]), "r"(b[0]), "r"(b[1]));
}
#define LDMX4(r0, r1, r2, r3, addr) \
    asm volatile("ldmatrix.sync.aligned.m8n8.x4.shared.b16 {%0,%1,%2,%3}, [%4];" \
                 : "=r"(r0), "=r"(r1), "=r"(r2), "=r"(r3) : "r"(addr))

__device__ __forceinline__ void split_bf16(float v, __nv_bfloat16& h, __nv_bfloat16& l) {
    h = __float2bfloat16(v);
    l = __float2bfloat16(v - __bfloat162float(h));
}
__device__ __forceinline__ uint32_t b2u(__nv_bfloat162 v) {
    return *reinterpret_cast<uint32_t*>(&v);
}
__device__ __forceinline__ void split_pack(float a, float b, uint32_t& hi, uint32_t& lo) {
    __nv_bfloat162 h = __floats2bfloat162_rn(a, b);
    __nv_bfloat162 l = __floats2bfloat162_rn(a - __bfloat162float(h.x),
                                             b - __bfloat162float(h.y));
    hi = b2u(h); lo = b2u(l);
}
// fp16 hi/lo split (for proj A operand)
__device__ __forceinline__ void split_pack_h(float a, float b, uint32_t& hi, uint32_t& lo) {
    __half2 h = __floats2half2_rn(a, b);
    __half2 l = __floats2half2_rn(a - __half2float(__low2half(h)),
                                  b - __half2float(__high2half(h)));
    hi = *reinterpret_cast<uint32_t*>(&h);
    lo = *reinterpret_cast<uint32_t*>(&l);
}

// ---------------------------------------------------------------------------
// Fused prep: one launch, three roles.
//  bid [0, 8192):       x fp32 -> unified tiled bf16
//  bid [8192, 11264):   Wqkv^T tsplit (bf16 hi/lo)
//  bid [11264, 12288):  Wproj^T tsplit (single fp16, 64k rows)
// ---------------------------------------------------------------------------
#define PREP_X_BLOCKS 8192
#define PREP_WQ_BLOCKS 3072
#define PREP_WP_BLOCKS 1024

__global__ __launch_bounds__(256) void prep_all(
    const float4* __restrict__ x, char* __restrict__ xd,
    const float* __restrict__ Wq, char* __restrict__ wqd,
    const float* __restrict__ Wp, char* __restrict__ wpd)
{
    const int bid = blockIdx.x;
    const int tid = threadIdx.x;

    if (bid < PREP_X_BLOCKS) {
        const int K = CDIM;
        const int i = bid * 256 + tid;
        const int n4 = MROWS * CDIM / 4;
        if (i >= n4) return;
        const int K4 = K >> 2;
        const int row = i / K4, k = (i % K4) << 2;
        float4 v = x[i];
        uint32_t h0, l0, h1, l1;
        split_pack(v.x, v.y, h0, l0);
        split_pack(v.z, v.w, h1, l1);
        *reinterpret_cast<uint2*>(xd + utile_off(row, k, K, 0)) = make_uint2(h0, h1);
        *reinterpret_cast<uint2*>(xd + utile_off(row, k, K, 1)) = make_uint2(l0, l1);
        return;
    }

    __shared__ float t[32][33];
    const int tx = tid & 31, ty = tid >> 5;
    const int nl = tid >> 3, kl = (tid & 7) << 2;

    if (bid < PREP_X_BLOCKS + PREP_WQ_BLOCKS) {
        // ---- Wqkv role (bf16 hi/lo, 32k layout) ----
        const int idx = bid - PREP_X_BLOCKS;
        const int Nn = 3 * CDIM;
        const int bx = idx % (3 * CDIM / 32), by = idx / (3 * CDIM / 32);
        const int n0 = bx * 32, k0 = by * 32;
        #pragma unroll
        for (int i = 0; i < 4; i++) {
            const int k = k0 + ty + i * 8;
            t[ty + i * 8][tx] = Wq[(size_t)k * Nn + n0 + tx];
        }
        __syncthreads();
        uint32_t h0, l0, h1, l1;
        split_pack(t[kl][nl],     t[kl + 1][nl], h0, l0);
        split_pack(t[kl + 2][nl], t[kl + 3][nl], h1, l1);
        *reinterpret_cast<uint2*>(wqd + utile_off(n0 + nl, k0 + kl, CDIM, 0)) = make_uint2(h0, h1);
        *reinterpret_cast<uint2*>(wqd + utile_off(n0 + nl, k0 + kl, CDIM, 1)) = make_uint2(l0, l1);
    } else {
        // ---- Wproj role (single fp16, 64k layout) ----
        const int idx = bid - PREP_X_BLOCKS - PREP_WQ_BLOCKS;
        const int Nn = CDIM;
        const int bx = idx % (CDIM / 32), by = idx / (CDIM / 32);
        const int n0 = bx * 32, k0 = by * 32;
        #pragma unroll
        for (int i = 0; i < 4; i++) {
            const int k = k0 + ty + i * 8;
            t[ty + i * 8][tx] = Wp[(size_t)k * Nn + n0 + tx];
        }
        __syncthreads();
        __half2 p0 = __floats2half2_rn(t[kl][nl],     t[kl + 1][nl]);
        __half2 p1 = __floats2half2_rn(t[kl + 2][nl], t[kl + 3][nl]);
        *reinterpret_cast<uint2*>(wpd + wtile_off(n0 + nl, k0 + kl)) =
            make_uint2(*reinterpret_cast<uint32_t*>(&p0), *reinterpret_cast<uint32_t*>(&p1));
    }
}

// ---------------------------------------------------------------------------
// Shared GEMM mainloop (qkv): 3-stage bulk pipeline, bf16 3-pass.
// ---------------------------------------------------------------------------
__device__ __forceinline__ void gemm_mainloop(
    uint32_t sb, int tid, int wid, int lane,
    const char* Ahl, const char* Bhl,
    size_t tbA, size_t tbB, int Kc, float cfr[2][8][4])
{
    const int wm = wid & 3, wn = wid >> 2;

    const uint32_t lA = (uint32_t)((lane & 7) + ((lane >> 3) & 1) * 8);
    const uint32_t cA = (uint32_t)(lane >> 4);
    const uint32_t lB = (uint32_t)((lane & 7) + (lane >> 4) * 8);
    const uint32_t cB = (uint32_t)((lane >> 3) & 1);

    auto produce = [&](int p) {
        const int s = p % 3;
        const uint32_t st = sb + 1024 + s * 32768;
        mbar_expect(sb + s * 8, 32768);
        bulk_g2s(st,         Ahl + (tbA + p) * 16384, 16384, sb + s * 8);
        bulk_g2s(st + 16384, Bhl + (tbB + p) * 16384, 16384, sb + s * 8);
    };

    if (tid == 0) { produce(0); produce(1); }

    for (int c = 0; c < Kc; c++) {
        const int cs = c % 3, cph = (c / 3) & 1;
        if (tid == 0) {
            const int p = c + 2;
            if (p < Kc) {
                const int ps = p % 3;
                if (p >= 3) mbar_wait(sb + 32 + ps * 8, (uint32_t)(((p / 3) - 1) & 1));
                produce(p);
            }
        }
        mbar_wait(sb + cs * 8, (uint32_t)cph);

        const uint32_t st = sb + 1024 + cs * 32768;
        #pragma unroll
        for (int ks = 0; ks < 2; ks++) {
            uint32_t ah[2][4], al[2][4];
            #pragma unroll
            for (int mt = 0; mt < 2; mt++) {
                const uint32_t row = (uint32_t)(wm * 32 + mt * 16) + lA;
                const uint32_t rb = st + row * 128;
                LDMX4(ah[mt][0], ah[mt][1], ah[mt][2], ah[mt][3],
                      rb + (((2 * ks + cA) ^ (row & 7)) << 4));
                LDMX4(al[mt][0], al[mt][1], al[mt][2], al[mt][3],
                      rb + (((2 * ks + cA + 4) ^ (row & 7)) << 4));
            }
            #pragma unroll
            for (int p = 0; p < 4; p++) {
                const uint32_t row = (uint32_t)(wn * 64 + p * 16) + lB;
                const uint32_t rb = st + 16384 + row * 128;
                uint32_t h0, h1, h2, h3, l0, l1, l2, l3;
                LDMX4(h0, h1, h2, h3, rb + (((2 * ks + cB) ^ (row & 7)) << 4));
                LDMX4(l0, l1, l2, l3, rb + (((2 * ks + cB + 4) ^ (row & 7)) << 4));
                uint32_t bh0[2] = {h0, h1}, bh1[2] = {h2, h3};
                uint32_t bl0[2] = {l0, l1}, bl1[2] = {l2, l3};
                #pragma unroll
                for (int mt = 0; mt < 2; mt++) {
                    mma16816(cfr[mt][2 * p],     ah[mt], bh0);
                    mma16816(cfr[mt][2 * p],     ah[mt], bl0);
                    mma16816(cfr[mt][2 * p],     al[mt], bh0);
                    mma16816(cfr[mt][2 * p + 1], ah[mt], bh1);
                    mma16816(cfr[mt][2 * p + 1], ah[mt], bl1);
                    mma16816(cfr[mt][2 * p + 1], al[mt], bh1);
                }
            }
        }
        mbar_arrive(sb + 32 + cs * 8);
    }
}

__device__ __forceinline__ void gemm_barrier_init3(uint32_t sb, int tid) {
    if (tid == 0) {
        #pragma unroll
        for (int s = 0; s < 3; s++) {
            mbar_init(sb + s * 8, 1);
            mbar_init(sb + 32 + s * 8, 256);
        }
        asm volatile("fence.proxy.async.shared::cta;" ::: "memory");
    }
    __syncthreads();
}

// ---------------------------------------------------------------------------
// Projection GEMM: fp16 2-pass (A = attn out hi/lo fp16, B = Wp single fp16).
// A tiles 32k (16KB each, 2 per chunk), B tiles 64k (16KB). Stage = 48KB.
// 2-stage pipeline, 2 CTAs/SM. Kc = 16 chunks of 64 k.
// ---------------------------------------------------------------------------
__global__ __launch_bounds__(256, 2) void gemm_proj(
    const char* __restrict__ Ahl, const char* __restrict__ Bh,
    const float* __restrict__ bias, float* __restrict__ Cout)
{
    extern __shared__ char smem[];
    const uint32_t sb = smem_u32(smem);
    const int tid = threadIdx.x, wid = tid >> 5, lane = tid & 31;
    const int gid = lane >> 2, tig = lane & 3;
    const int wm = wid & 3, wn = wid >> 2;
    constexpr int Nn = CDIM;

    if (tid == 0) {
        #pragma unroll
        for (int s = 0; s < 2; s++) {
            mbar_init(sb + s * 8, 1);
            mbar_init(sb + 16 + s * 8, 256);
        }
        asm volatile("fence.proxy.async.shared::cta;" ::: "memory");
    }
    __syncthreads();

    const uint32_t lA = (uint32_t)((lane & 7) + ((lane >> 3) & 1) * 8);
    const uint32_t cA = (uint32_t)(lane >> 4);
    const uint32_t lB = (uint32_t)((lane & 7) + (lane >> 4) * 8);
    const uint32_t cB = (uint32_t)((lane >> 3) & 1);

    const size_t tbA = (size_t)blockIdx.y * 32;   // 32 A-chunks (32k) per blk row
    const size_t tbB = (size_t)blockIdx.x * 16;   // 16 B-tiles (64k) per blk row

    auto produce = [&](int p) {
        const int s = p & 1;
        const uint32_t st = sb + 1024 + s * 49152;
        mbar_expect(sb + s * 8, 49152);
        bulk_g2s(st,         Ahl + (tbA + 2 * p) * 16384,     16384, sb + s * 8);
        bulk_g2s(st + 16384, Ahl + (tbA + 2 * p + 1) * 16384, 16384, sb + s * 8);
        bulk_g2s(st + 32768, Bh + (tbB + p) * 16384,          16384, sb + s * 8);
    };

    if (tid == 0) { produce(0); produce(1); }

    float cfr[2][8][4];
    #pragma unroll
    for (int mt = 0; mt < 2; mt++)
        #pragma unroll
        for (int nt = 0; nt < 8; nt++)
            #pragma unroll
            for (int q = 0; q < 4; q++) cfr[mt][nt][q] = 0.f;

    for (int c = 0; c < 16; c++) {
        const int cs = c & 1;
        mbar_wait(sb + cs * 8, (uint32_t)((c >> 1) & 1));

        const uint32_t st = sb + 1024 + cs * 49152;
        #pragma unroll
        for (int ks = 0; ks < 4; ks++) {
            const int asel = ks >> 1, kk = ks & 1;
            uint32_t ah[2][4], al[2][4];
            #pragma unroll
            for (int mt = 0; mt < 2; mt++) {
                const uint32_t row = (uint32_t)(wm * 32 + mt * 16) + lA;
                const uint32_t rb = st + asel * 16384 + row * 128;
                LDMX4(ah[mt][0], ah[mt][1], ah[mt][2], ah[mt][3],
                      rb + (((2 * kk + cA) ^ (row & 7)) << 4));
                LDMX4(al[mt][0], al[mt][1], al[mt][2], al[mt][3],
                      rb + (((2 * kk + cA + 4) ^ (row & 7)) << 4));
            }
            #pragma unroll
            for (int p = 0; p < 4; p++) {
                const uint32_t row = (uint32_t)(wn * 64 + p * 16) + lB;
                const uint32_t rb = st + 32768 + row * 128;
                uint32_t h0, h1, h2, h3;
                LDMX4(h0, h1, h2, h3, rb + (((2 * ks + cB) ^ (row & 7)) << 4));
                uint32_t bh0[2] = {h0, h1}, bh1[2] = {h2, h3};
                #pragma unroll
                for (int mt = 0; mt < 2; mt++) {
                    mma16816h(cfr[mt][2 * p],     ah[mt], bh0);
                    mma16816h(cfr[mt][2 * p],     al[mt], bh0);
                    mma16816h(cfr[mt][2 * p + 1], ah[mt], bh1);
                    mma16816h(cfr[mt][2 * p + 1], al[mt], bh1);
                }
            }
        }
        mbar_arrive(sb + 16 + cs * 8);
        if (tid == 0 && c + 2 < 16) {
            mbar_wait(sb + 16 + cs * 8, (uint32_t)((c >> 1) & 1));
            produce(c + 2);
        }
    }

    const int m0 = blockIdx.y * 128, n0 = blockIdx.x * 128;
    #pragma unroll
    for (int mt = 0; mt < 2; mt++) {
        const int r = m0 + wm * 32 + mt * 16 + gid;
        #pragma unroll
        for (int nt = 0; nt < 8; nt++) {
            const int col = n0 + wn * 64 + nt * 8 + tig * 2;
            const float b0 = bias[col], b1 = bias[col + 1];
            *reinterpret_cast<float2*>(&Cout[(size_t)r * Nn + col]) =
                make_float2(cfr[mt][nt][0] + b0, cfr[mt][nt][1] + b1);
            *reinterpret_cast<float2*>(&Cout[(size_t)(r + 8) * Nn + col]) =
                make_float2(cfr[mt][nt][2] + b0, cfr[mt][nt][3] + b1);
        }
    }
}

// ---------------------------------------------------------------------------
// QKV GEMM with fused flash-tile epilogue (Q scaled by QSCALE).
// ---------------------------------------------------------------------------
__global__ __launch_bounds__(256, 2) void gemm_qkv(
    const char* __restrict__ Ahl, const char* __restrict__ Bhl,
    char* __restrict__ fq, char* __restrict__ fk, char* __restrict__ fv)
{
    extern __shared__ char smem[];
    const uint32_t sb = smem_u32(smem);
    const int tid = threadIdx.x, wid = tid >> 5, lane = tid & 31;
    const int gid = lane >> 2, tig = lane & 3;
    const int wm = wid & 3, wn = wid >> 2;
    constexpr int Kc = CDIM >> 5;  // 32

    gemm_barrier_init3(sb, tid);

    float cfr[2][8][4];
    #pragma unroll
    for (int mt = 0; mt < 2; mt++)
        #pragma unroll
        for (int nt = 0; nt < 8; nt++)
            #pragma unroll
            for (int q = 0; q < 4; q++) cfr[mt][nt][q] = 0.f;

    gemm_mainloop(sb, tid, wid, lane, Ahl, Bhl,
                  (size_t)blockIdx.y * Kc, (size_t)blockIdx.x * Kc, Kc, cfr);

    const int b = blockIdx.y >> 4, tile = blockIdx.y & 15;
    const int bx = blockIdx.x;

    if (bx < 16) {
        const bool isQ = bx < 8;
        const int j = isQ ? bx : bx - 8;
        char* const fbase = isQ ? fq : fk;
        const float sc = isQ ? QSCALE : 1.0f;
        #pragma unroll
        for (int mt = 0; mt < 2; mt++) {
            const int rA = wm * 32 + mt * 16 + gid;
            #pragma unroll
            for (int nt = 0; nt < 8; nt++) {
                const int c = wn * 64 + nt * 8 + tig * 2;
                const int h = 2 * j + (c >> 6);
                const int d = c & 63;
                char* dst = fbase + (((size_t)b * NHEADS + h) * 16 + tile) * 32768;
                const int kc = d >> 5, chunk = (d & 31) >> 3, bo = (d & 7) * 2;
                uint32_t hi0, lo0, hi1, lo1;
                split_pack(cfr[mt][nt][0] * sc, cfr[mt][nt][1] * sc, hi0, lo0);
                split_pack(cfr[mt][nt][2] * sc, cfr[mt][nt][3] * sc, hi1, lo1);
                char* baseA = dst + kc * 16384 + rA * 128;
                char* baseB = dst + kc * 16384 + (rA + 8) * 128;
                *reinterpret_cast<uint32_t*>(baseA + (((chunk)     ^ (rA & 7)) << 4) + bo) = hi0;
                *reinterpret_cast<uint32_t*>(baseA + (((chunk + 4) ^ (rA & 7)) << 4) + bo) = lo0;
                *reinterpret_cast<uint32_t*>(baseB + (((chunk)     ^ ((rA + 8) & 7)) << 4) + bo) = hi1;
                *reinterpret_cast<uint32_t*>(baseB + (((chunk + 4) ^ ((rA + 8) & 7)) << 4) + bo) = lo1;
            }
        }
    } else {
        const int j = bx - 16;
        float* vs = reinterpret_cast<float*>(smem + 1024);
        constexpr int VST = 130;
        __syncthreads();
        #pragma unroll
        for (int mt = 0; mt < 2; mt++) {
            const int rA = wm * 32 + mt * 16 + gid;
            #pragma unroll
            for (int nt = 0; nt < 8; nt++) {
                const int c = wn * 64 + nt * 8 + tig * 2;
                vs[rA * VST + c]           = cfr[mt][nt][0];
                vs[rA * VST + c + 1]       = cfr[mt][nt][1];
                vs[(rA + 8) * VST + c]     = cfr[mt][nt][2];
                vs[(rA + 8) * VST + c + 1] = cfr[mt][nt][3];
            }
        }
        __syncthreads();
        for (int it = tid; it < 4096; it += 256) {
            const int hsel = it >> 11, rem = it & 2047;
            const int d = rem >> 5, k4 = (rem & 31) * 4;
            const int cc = hsel * 64 + d;
            float4 v = make_float4(vs[k4 * VST + cc], vs[(k4 + 1) * VST + cc],
                                   vs[(k4 + 2) * VST + cc], vs[(k4 + 3) * VST + cc]);
            uint32_t h0, l0, h1, l1;
            split_pack(v.x, v.y, h0, l0);
            split_pack(v.z, v.w, h1, l1);
            char* vdst = fv + (((size_t)b * NHEADS + 2 * j + hsel) * 16 + tile) * 32768;
            const int kc = k4 >> 5, chunk = (k4 & 31) >> 3, bo = (k4 & 7) * 2;
            char* base = vdst + kc * 8192 + d * 128;
            *reinterpret_cast<uint2*>(base + (((chunk)     ^ (d & 7)) << 4) + bo) =
                make_uint2(h0, h1);
            *reinterpret_cast<uint2*>(base + (((chunk + 4) ^ (d & 7)) << 4) + bo) =
                make_uint2(l0, l1);
        }
    }
}

// ---------------------------------------------------------------------------
// HMMA flash attention: 128-key tiles, 2-stage pipeline, 1 CTA/SM.
// Per-kc exp/repack interleaved with PV MMAs. Epilogue emits fp16 hi/lo.
// ---------------------------------------------------------------------------
__global__ __launch_bounds__(256, 1) void flash_hmma(
    const char* __restrict__ fq, const char* __restrict__ fk,
    const char* __restrict__ fv, const int* __restrict__ mask,
    char* __restrict__ outt)
{
    extern __shared__ char smem[];
    const uint32_t sb = smem_u32(smem);
    const int tid = threadIdx.x, w = tid >> 5, lane = tid & 31;
    const int gid = lane >> 2, tig = lane & 3;
    const int qt = blockIdx.x, h = blockIdx.y, b = blockIdx.z;
    const size_t bh = (size_t)b * NHEADS + h;

    const uint32_t QS = sb + 1024;
    const uint32_t ST0 = QS + 32768;
    constexpr uint32_t STG = 66560;

    if (tid == 0) {
        mbar_init(sb + 0, 1);
        mbar_init(sb + 8, 1);  mbar_init(sb + 16, 1);
        mbar_init(sb + 24, 256); mbar_init(sb + 32, 256);
        asm volatile("fence.proxy.async.shared::cta;" ::: "memory");
    }
    __syncthreads();

    auto produce = [&](int kt) {
        const int s = kt & 1;
        const uint32_t st = ST0 + s * STG;
        mbar_expect(sb + 8 + s * 8, 65536 + 512);
        bulk_g2s(st,         fk + (bh * 16 + kt) * 32768, 32768, sb + 8 + s * 8);
        bulk_g2s(st + 32768, fv + (bh * 16 + kt) * 32768, 32768, sb + 8 + s * 8);
        bulk_g2s(st + 65536, (const char*)(mask + b * NDIM + kt * 128), 512, sb + 8 + s * 8);
    };

    if (tid == 0) {
        mbar_expect(sb + 0, 32768);
        bulk_g2s(QS, fq + (bh * 16 + qt) * 32768, 32768, sb + 0);
        produce(0); produce(1);
    }

    mbar_wait(sb + 0, 0);
    uint32_t qh[4][4], ql[4][4];
    {
        const uint32_t r0 = (uint32_t)(w * 16 + gid);
        #pragma unroll
        for (int ks = 0; ks < 4; ks++) {
            const uint32_t kc = ks >> 1, cb = 2 * (ks & 1);
            const uint32_t a0 = QS + kc * 16384 + tig * 4;
            const uint32_t rA = r0, rB = r0 + 8;
            qh[ks][0] = lds32(a0 + rA * 128 + (((cb)     ^ (rA & 7)) << 4));
            qh[ks][1] = lds32(a0 + rB * 128 + (((cb)     ^ (rB & 7)) << 4));
            qh[ks][2] = lds32(a0 + rA * 128 + (((cb + 1) ^ (rA & 7)) << 4));
            qh[ks][3] = lds32(a0 + rB * 128 + (((cb + 1) ^ (rB & 7)) << 4));
            ql[ks][0] = lds32(a0 + rA * 128 + (((cb + 4) ^ (rA & 7)) << 4));
            ql[ks][1] = lds32(a0 + rB * 128 + (((cb + 4) ^ (rB & 7)) << 4));
            ql[ks][2] = lds32(a0 + rA * 128 + (((cb + 5) ^ (rA & 7)) << 4));
            ql[ks][3] = lds32(a0 + rB * 128 + (((cb + 5) ^ (rB & 7)) << 4));
        }
    }

    float o[8][4];
    #pragma unroll
    for (int nt = 0; nt < 8; nt++)
        #pragma unroll
        for (int q = 0; q < 4; q++) o[nt][q] = 0.f;
    float mi0 = -1e30f, mi1 = -1e30f, li0 = 0.f, li1 = 0.f;

    const uint32_t lrow = (uint32_t)(lane & 7);
    const uint32_t lch = (uint32_t)(lane >> 3);

    #pragma unroll 1
    for (int kt = 0; kt < 16; kt++) {
        const int s = kt & 1;
        mbar_wait(sb + 8 + s * 8, (uint32_t)((kt >> 1) & 1));
        const uint32_t kbse = ST0 + s * STG;
        const uint32_t vbse = kbse + 32768;
        const uint32_t mbse = kbse + 65536;

        float sf[16][4];
        #pragma unroll
        for (int j = 0; j < 16; j++) {
            sf[j][0] = sf[j][1] = sf[j][2] = sf[j][3] = 0.f;
            const uint32_t row = (uint32_t)(j * 8) + lrow;
            #pragma unroll
            for (int kc = 0; kc < 2; kc++) {
                const uint32_t rb = kbse + kc * 16384 + row * 128;
                uint32_t h0, h1, h2, h3, l0, l1, l2, l3;
                LDMX4(h0, h1, h2, h3, rb + (((lch)     ^ (row & 7)) << 4));
                LDMX4(l0, l1, l2, l3, rb + (((lch + 4) ^ (row & 7)) << 4));
                uint32_t bh0[2] = {h0, h1}, bh1[2] = {h2, h3};
                uint32_t bl0[2] = {l0, l1}, bl1[2] = {l2, l3};
                mma16816(sf[j], qh[2 * kc],     bh0);
                mma16816(sf[j], qh[2 * kc],     bl0);
                mma16816(sf[j], ql[2 * kc],     bh0);
                mma16816(sf[j], qh[2 * kc + 1], bh1);
                mma16816(sf[j], qh[2 * kc + 1], bl1);
                mma16816(sf[j], ql[2 * kc + 1], bh1);
            }
        }

        #pragma unroll
        for (int j = 0; j < 16; j++) {
            const uint32_t ma = mbse + (uint32_t)(j * 8 + 2 * tig) * 4;
            if ((int)lds32(ma) > 0)     { sf[j][0] = MASKVAL; sf[j][2] = MASKVAL; }
            if ((int)lds32(ma + 4) > 0) { sf[j][1] = MASKVAL; sf[j][3] = MASKVAL; }
        }

        float rm0 = -1e30f, rm1 = -1e30f;
        #pragma unroll
        for (int j = 0; j < 16; j++) {
            rm0 = fmaxf(rm0, fmaxf(sf[j][0], sf[j][1]));
            rm1 = fmaxf(rm1, fmaxf(sf[j][2], sf[j][3]));
        }
        rm0 = fmaxf(rm0, __shfl_xor_sync(0xffffffffu, rm0, 1));
        rm0 = fmaxf(rm0, __shfl_xor_sync(0xffffffffu, rm0, 2));
        rm1 = fmaxf(rm1, __shfl_xor_sync(0xffffffffu, rm1, 1));
        rm1 = fmaxf(rm1, __shfl_xor_sync(0xffffffffu, rm1, 2));
        const float mn0 = fmaxf(mi0, rm0), mn1 = fmaxf(mi1, rm1);
        const float a0 = ex2f(mi0 - mn0), a1 = ex2f(mi1 - mn1);
        mi0 = mn0; mi1 = mn1;
        #pragma unroll
        for (int nt = 0; nt < 8; nt++) {
            o[nt][0] *= a0; o[nt][1] *= a0;
            o[nt][2] *= a1; o[nt][3] *= a1;
        }

        float rs0 = 0.f, rs1 = 0.f;
        #pragma unroll
        for (int kc = 0; kc < 4; kc++) {
            uint32_t pah[2][4], pal[2][4];
            #pragma unroll
            for (int jj = 0; jj < 2; jj++) {
                const int j0 = 4 * kc + 2 * jj;
                sf[j0][0] = ex2f(sf[j0][0] - mn0); rs0 += sf[j0][0];
                sf[j0][1] = ex2f(sf[j0][1] - mn0); rs0 += sf[j0][1];
                sf[j0][2] = ex2f(sf[j0][2] - mn1); rs1 += sf[j0][2];
                sf[j0][3] = ex2f(sf[j0][3] - mn1); rs1 += sf[j0][3];
                sf[j0 + 1][0] = ex2f(sf[j0 + 1][0] - mn0); rs0 += sf[j0 + 1][0];
                sf[j0 + 1][1] = ex2f(sf[j0 + 1][1] - mn0); rs0 += sf[j0 + 1][1];
                sf[j0 + 1][2] = ex2f(sf[j0 + 1][2] - mn1); rs1 += sf[j0 + 1][2];
                sf[j0 + 1][3] = ex2f(sf[j0 + 1][3] - mn1); rs1 += sf[j0 + 1][3];
                split_pack(sf[j0][0],     sf[j0][1],     pah[jj][0], pal[jj][0]);
                split_pack(sf[j0][2],     sf[j0][3],     pah[jj][1], pal[jj][1]);
                split_pack(sf[j0 + 1][0], sf[j0 + 1][1], pah[jj][2], pal[jj][2]);
                split_pack(sf[j0 + 1][2], sf[j0 + 1][3], pah[jj][3], pal[jj][3]);
            }
            #pragma unroll
            for (int nt = 0; nt < 8; nt++) {
                const uint32_t row = (uint32_t)(nt * 8) + lrow;
                const uint32_t rb = vbse + kc * 8192 + row * 128;
                uint32_t h0, h1, h2, h3, l0, l1, l2, l3;
                LDMX4(h0, h1, h2, h3, rb + (((lch)     ^ (row & 7)) << 4));
                LDMX4(l0, l1, l2, l3, rb + (((lch + 4) ^ (row & 7)) << 4));
                uint32_t vh0[2] = {h0, h1}, vh1[2] = {h2, h3};
                uint32_t vl0[2] = {l0, l1}, vl1[2] = {l2, l3};
                mma16816(o[nt], pah[0], vh0);
                mma16816(o[nt], pah[0], vl0);
                mma16816(o[nt], pal[0], vh0);
                mma16816(o[nt], pah[1], vh1);
                mma16816(o[nt], pah[1], vl1);
                mma16816(o[nt], pal[1], vh1);
            }
        }

        rs0 += __shfl_xor_sync(0xffffffffu, rs0, 1);
        rs0 += __shfl_xor_sync(0xffffffffu, rs0, 2);
        rs1 += __shfl_xor_sync(0xffffffffu, rs1, 1);
        rs1 += __shfl_xor_sync(0xffffffffu, rs1, 2);
        li0 = li0 * a0 + rs0;
        li1 = li1 * a1 + rs1;

        mbar_arrive(sb + 24 + s * 8);
        if (tid == 0 && kt + 2 < 16) {
            mbar_wait(sb + 24 + s * 8, (uint32_t)((kt >> 1) & 1));
            produce(kt + 2);
        }
    }

    // ---- epilogue: normalize, emit unified tiled fp16 (hi|lo) for proj ----
    const float inv0 = 1.f / li0, inv1 = 1.f / li1;
    const int row0 = b * NDIM + qt * 128 + w * 16 + gid;
    #pragma unroll
    for (int nt = 0; nt < 8; nt++) {
        const int col = h * 64 + nt * 8 + tig * 2;
        uint32_t h0, l0, h1, l1;
        split_pack_h(o[nt][0] * inv0, o[nt][1] * inv0, h0, l0);
        split_pack_h(o[nt][2] * inv1, o[nt][3] * inv1, h1, l1);
        *reinterpret_cast<uint32_t*>(outt + utile_off(row0, col, CDIM, 0)) = h0;
        *reinterpret_cast<uint32_t*>(outt + utile_off(row0, col, CDIM, 1)) = l0;
        *reinterpret_cast<uint32_t*>(outt + utile_off(row0 + 8, col, CDIM, 0)) = h1;
        *reinterpret_cast<uint32_t*>(outt + utile_off(row0 + 8, col, CDIM, 1)) = l1;
    }
}

// ---------------------------------------------------------------------------
extern "C" void kernel_launch(void* const* d_in, const int* in_sizes, int n_in,
                              void* d_out, int out_size)
{
    const float* x     = (const float*)d_in[0];
    const float* Wqkv  = (const float*)d_in[1];
    const float* Wproj = (const float*)d_in[2];
    const float* bproj = (const float*)d_in[3];
    const int*   mask  = (const int*)d_in[4];
    float* out = (float*)d_out;

    const int B = BDIM, N = NDIM, C = CDIM, M = MROWS;

    char *x_p, *wq_p, *wp_p, *att_p, *fq_p, *fk_p, *fv_p;
    cudaGetSymbolAddress((void**)&x_p, g_x);
    cudaGetSymbolAddress((void**)&wq_p, g_wq);
    cudaGetSymbolAddress((void**)&wp_p, g_wp);
    cudaGetSymbolAddress((void**)&att_p, g_att);
    cudaGetSymbolAddress((void**)&fq_p, g_fq);
    cudaGetSymbolAddress((void**)&fk_p, g_fk);
    cudaGetSymbolAddress((void**)&fv_p, g_fv);

    // 0) Fused prep (single launch; three roles)
    prep_all<<<PREP_X_BLOCKS + PREP_WQ_BLOCKS + PREP_WP_BLOCKS, 256>>>(
        (const float4*)x, x_p, Wqkv, wq_p, Wproj, wp_p);

    const int gsmem = 1024 + 3 * 32768;
    cudaFuncSetAttribute(gemm_qkv, cudaFuncAttributeMaxDynamicSharedMemorySize, gsmem);

    // 1) QKV GEMM with fused flash-tile epilogue
    gemm_qkv<<<dim3(3 * C / 128, M / 128), 256, gsmem>>>(
        x_p, wq_p, fq_p, fk_p, fv_p);

    // 2) Flash attention (HMMA, ex2 softmax, 128-key tiles, 2-stage pipeline)
    const int fsmem = 1024 + 32768 + 2 * 66560;
    cudaFuncSetAttribute(flash_hmma, cudaFuncAttributeMaxDynamicSharedMemorySize, fsmem);
    flash_hmma<<<dim3(16, NHEADS, B), 256, fsmem>>>(
        fq_p, fk_p, fv_p, mask, att_p);

    // 3) Output projection (fp16 2-pass)
    const int psmem = 1024 + 2 * 49152;
    cudaFuncSetAttribute(gemm_proj, cudaFuncAttributeMaxDynamicSharedMemorySize, psmem);
    gemm_proj<<<dim3(C / 128, M / 128), 256, psmem>>>(att_p, wp_p, bproj, out);
}